// round 13
// baseline (speedup 1.0000x reference)
#include <cuda_runtime.h>
#include <math.h>
#include <stdint.h>

#define T_ 3
#define N_ 20000
#define F_ 256
#define FO_ 256
#define E_ 320000
#define R_ 4
#define C_ 5
#define MAT_ (F_*FO_)

// ---------------- scratch ----------------
__device__ float g_scores[T_*C_*N_];
__device__ float g_vals  [T_*C_*FO_];
__device__ int   g_tidx  [T_*C_*FO_];
__device__ float g_zt    [T_*C_*MAT_];
__device__ float g_upd   [C_*MAT_];
__device__ float g_rst   [C_*MAT_];
__device__ float g_Q  [2][C_*MAT_];
__device__ float g_Qc    [C_*MAT_];
__device__ float g_xc    [T_*N_*F_];
__device__ float g_Y     [R_*N_*FO_];
__device__ int   g_degI  [T_*R_*N_];
__device__ float g_dis   [T_*R_*N_];
__device__ float g_denom [C_];
__device__ int      g_cnt [T_*N_];
__device__ int      g_off [T_*(N_+1)];
__device__ int      g_fill[T_*N_];
__device__ uint32_t g_epack[T_*E_];

extern __shared__ unsigned char s_dyn[];

__device__ __forceinline__ uint32_t f2key(float f) {
    uint32_t u = __float_as_uint(f);
    return (u & 0x80000000u) ? ~u : (u | 0x80000000u);
}
__device__ __forceinline__ float key2f(uint32_t k) {
    return (k & 0x80000000u) ? __uint_as_float(k & 0x7FFFFFFFu) : __uint_as_float(~k);
}
__device__ __forceinline__ float cvt_tf32(float f) {
    uint32_t r;
    asm("cvt.rna.tf32.f32 %0, %1;" : "=r"(r) : "f"(f));
    return __uint_as_float(r);
}
__device__ __forceinline__ float sigmoidf_(float v) { return 1.f / (1.f + expf(-v)); }

__device__ __forceinline__ void mma_tf32(float* d, const uint32_t* a, uint32_t b0, uint32_t b1) {
    asm volatile(
        "mma.sync.aligned.m16n8k8.row.col.f32.tf32.tf32.f32 "
        "{%0,%1,%2,%3}, {%4,%5,%6,%7}, {%8,%9}, {%0,%1,%2,%3};"
        : "+f"(d[0]), "+f"(d[1]), "+f"(d[2]), "+f"(d[3])
        : "r"(a[0]), "r"(a[1]), "r"(a[2]), "r"(a[3]), "r"(b0), "r"(b1));
}
__device__ __forceinline__ uint32_t smem_u32(const void* p) {
    uint32_t a;
    asm("{ .reg .u64 t; cvta.to.shared.u64 t, %1; cvt.u32.u64 %0, t; }" : "=r"(a) : "l"(p));
    return a;
}
__device__ __forceinline__ void cp_async16(uint32_t dst, const void* src) {
    asm volatile("cp.async.ca.shared.global [%0], [%1], 16;" :: "r"(dst), "l"(src) : "memory");
}
#define CP_COMMIT()  asm volatile("cp.async.commit_group;" ::: "memory")
#define CP_WAIT(n)   asm volatile("cp.async.wait_group %0;" :: "n"(n) : "memory")

// ================== PREAMBLE ==================
#define PB_INIT  ((C_*MAT_)/256)
#define PB_XCVT  ((T_*N_*F_/4)/256)
#define PB_ZERO  (((T_*R_*N_)+255)/256)
#define PB_TOTAL (PB_INIT + PB_XCVT + PB_ZERO + C_)

__global__ __launch_bounds__(256) void k_prep(const float* __restrict__ Wself,
                                              const float* __restrict__ Wrel,
                                              const float* __restrict__ x,
                                              const float* __restrict__ s_sc,
                                              const float* __restrict__ r_sc) {
    int b = blockIdx.x, tid = threadIdx.x;
    if (b < PB_INIT) {
        int i = b*256 + tid;
        int c = i / MAT_, off = i - c*MAT_;
        g_Q[0][i] = (c == 0) ? Wself[off] : Wrel[(c-1)*MAT_ + off];
    } else if (b < PB_INIT + PB_XCVT) {
        int i = (b - PB_INIT)*256 + tid;
        float4 v = ((const float4*)x)[i];
        v.x = cvt_tf32(v.x); v.y = cvt_tf32(v.y);
        v.z = cvt_tf32(v.z); v.w = cvt_tf32(v.w);
        ((float4*)g_xc)[i] = v;
    } else if (b < PB_INIT + PB_XCVT + PB_ZERO) {
        int i = (b - PB_INIT - PB_XCVT)*256 + tid;
        if (i < T_*R_*N_) g_degI[i] = 0;
        if (i < T_*N_) g_cnt[i] = 0;
    } else {
        int c = b - (PB_INIT + PB_XCVT + PB_ZERO);
        const float* sc = (c == 0) ? s_sc : r_sc + (c-1)*F_;
        float v = sc[tid];
        __shared__ float red[256];
        red[tid] = v * v;
        __syncthreads();
        for (int o = 128; o > 0; o >>= 1) {
            if (tid < o) red[tid] += red[tid + o];
            __syncthreads();
        }
        if (tid == 0) g_denom[c] = sqrtf(red[0]) + 1e-8f;
    }
}

__global__ __launch_bounds__(256) void k_scores_edge(const float* __restrict__ x,
                                                     const float* __restrict__ mask,
                                                     const float* __restrict__ s_sc,
                                                     const float* __restrict__ r_sc,
                                                     const int* __restrict__ ei,
                                                     const int* __restrict__ et) {
    int b = blockIdx.x, tid = threadIdx.x;
    if (b < 7500) {
        int t = b / 2500, blk = b - t*2500;
        __shared__ float sc[C_][F_];
        for (int i = tid; i < C_*F_; i += 256) {
            int c = i / F_, f = i - c*F_;
            sc[c][f] = (c == 0) ? s_sc[f] : r_sc[(c-1)*F_ + f];
        }
        __syncthreads();
        int warp = tid >> 5, lane = tid & 31;
        int n = blk * 8 + warp;
        if (n >= N_) return;
        const float4* xr = (const float4*)(x + ((size_t)t*N_ + n) * F_);
        float acc[C_] = {0.f, 0.f, 0.f, 0.f, 0.f};
        #pragma unroll
        for (int q = 0; q < 2; q++) {
            float4 xv = xr[lane + q*32];
            int e0 = (lane + q*32) * 4;
            #pragma unroll
            for (int c = 0; c < C_; c++) {
                acc[c] += xv.x * sc[c][e0]   + xv.y * sc[c][e0+1]
                        + xv.z * sc[c][e0+2] + xv.w * sc[c][e0+3];
            }
        }
        #pragma unroll
        for (int c = 0; c < C_; c++) {
            float v = acc[c];
            for (int o = 16; o > 0; o >>= 1) v += __shfl_down_sync(0xffffffffu, v, o);
            if (lane == 0)
                g_scores[(size_t)(t*C_ + c)*N_ + n] = v / g_denom[c] + mask[(size_t)t*N_ + n];
        }
    } else {
        int idx = b - 7500;
        int t = idx / 1250;
        int e = (idx - t*1250)*256 + tid;
        if (e >= E_) return;
        int row = ei[(size_t)t*2*E_ + e];
        int r   = et[(size_t)t*E_ + e];
        atomicAdd(&g_degI[(t*R_ + r)*N_ + row], 1);
        atomicAdd(&g_cnt[t*N_ + row], 1);
    }
}

// ================== topk + scan + dis ==================
__device__ void topk_body(int tc) {
    uint32_t* s_keys = (uint32_t*)s_dyn;
    __shared__ int      hist[256];
    __shared__ int      sfx[256];
    __shared__ uint32_t selKey[256];
    __shared__ int      selIdx[256];
    __shared__ uint32_t s_prefix;
    __shared__ int      s_remaining, s_eqCount, s_idxTh, s_cnt;

    int tid = threadIdx.x;
    const float* sc = g_scores + (size_t)tc * N_;

    if (tid < 256) hist[tid] = 0;
    if (tid == 0) { s_prefix = 0u; s_remaining = FO_; s_idxTh = 0x7FFFFFFF; s_eqCount = FO_; }
    __syncthreads();

    for (int i = tid; i < N_; i += 1024) {
        uint32_t k = f2key(sc[i]);
        s_keys[i] = k;
        atomicAdd(&hist[k >> 24], 1);
    }
    __syncthreads();

    #pragma unroll
    for (int pass = 3; pass >= 0; pass--) {
        int shift = pass * 8;
        if (pass < 3) {
            if (tid < 256) hist[tid] = 0;
            __syncthreads();
            uint32_t prefix = s_prefix;
            uint32_t pmask = 0xFFFFFFFFu << (shift + 8);
            for (int i = tid; i < N_; i += 1024) {
                uint32_t k = s_keys[i];
                if ((k & pmask) == (prefix & pmask))
                    atomicAdd(&hist[(k >> shift) & 0xFF], 1);
            }
            __syncthreads();
        }
        if (tid < 256) sfx[tid] = hist[tid];
        __syncthreads();
        #pragma unroll
        for (int o = 1; o < 256; o <<= 1) {
            int v = 0;
            if (tid < 256) v = sfx[tid] + ((tid + o < 256) ? sfx[tid + o] : 0);
            __syncthreads();
            if (tid < 256) sfx[tid] = v;
            __syncthreads();
        }
        int rem = s_remaining;
        __syncthreads();
        if (tid < 256) {
            int s  = sfx[tid];
            int sn = (tid < 255) ? sfx[tid + 1] : 0;
            if (s >= rem && sn < rem) {
                s_prefix |= ((uint32_t)tid) << shift;
                s_remaining = rem - sn;
                if (pass == 0) s_eqCount = hist[tid];
            }
        }
        __syncthreads();
    }
    uint32_t kth = s_prefix;
    int need = s_remaining;

    if (need < s_eqCount) {
        if (tid == 0) { s_prefix = 0u; s_remaining = need; }
        __syncthreads();
        #pragma unroll
        for (int pass = 1; pass >= 0; pass--) {
            int shift = pass * 8;
            if (tid < 256) hist[tid] = 0;
            __syncthreads();
            uint32_t prefixI = s_prefix;
            for (int i = tid; i < N_; i += 1024) {
                if (s_keys[i] == kth) {
                    if (pass == 1 || (((uint32_t)i >> 8) & 0xFF) == ((prefixI >> 8) & 0xFF))
                        atomicAdd(&hist[((uint32_t)i >> shift) & 0xFF], 1);
                }
            }
            __syncthreads();
            if (tid == 0) {
                int rem = s_remaining;
                uint32_t pfx = s_prefix;
                for (int bb = 0; bb < 256; bb++) {
                    int cnt = hist[bb];
                    if (cnt >= rem) { pfx |= ((uint32_t)bb) << shift; break; }
                    rem -= cnt;
                }
                s_remaining = rem;
                s_prefix = pfx;
            }
            __syncthreads();
        }
        if (tid == 0) s_idxTh = (int)s_prefix;
    }
    if (tid == 0) s_cnt = 0;
    __syncthreads();
    int idxTh = s_idxTh;

    for (int i = tid; i < N_; i += 1024) {
        uint32_t k = s_keys[i];
        if (k > kth || (k == kth && i <= idxTh)) {
            int p = atomicAdd(&s_cnt, 1);
            selKey[p] = k;
            selIdx[p] = i;
        }
    }
    __syncthreads();

    for (int k = 2; k <= 256; k <<= 1) {
        for (int j = k >> 1; j > 0; j >>= 1) {
            if (tid < 256) {
                int ixj = tid ^ j;
                if (ixj > tid) {
                    bool desc = ((tid & k) == 0);
                    uint32_t ka = selKey[tid], kb = selKey[ixj];
                    int ia = selIdx[tid], ib = selIdx[ixj];
                    bool aGreater = (ka > kb) || (ka == kb && ia < ib);
                    bool doswap = desc ? !aGreater : aGreater;
                    if (doswap) {
                        selKey[tid] = kb; selKey[ixj] = ka;
                        selIdx[tid] = ib; selIdx[ixj] = ia;
                    }
                }
            }
            __syncthreads();
        }
    }

    if (tid < 256) {
        g_vals[(size_t)tc*FO_ + tid] = key2f(selKey[tid]);
        g_tidx[(size_t)tc*FO_ + tid] = selIdx[tid];
    }
}

__device__ void scan_body(int t) {
    __shared__ int part[1024];
    const int* cnt = g_cnt + t*N_;
    int* off = g_off + t*(N_+1);
    int* fill = g_fill + t*N_;
    int tid = threadIdx.x;
    const int CH = (N_ + 1023) / 1024;
    int base = tid * CH;
    int s = 0;
    for (int i = 0; i < CH; i++) {
        int idx = base + i;
        if (idx < N_) s += cnt[idx];
    }
    part[tid] = s;
    __syncthreads();
    for (int o = 1; o < 1024; o <<= 1) {
        int v = (tid >= o) ? part[tid - o] : 0;
        __syncthreads();
        part[tid] += v;
        __syncthreads();
    }
    int run = (tid == 0) ? 0 : part[tid - 1];
    for (int i = 0; i < CH; i++) {
        int idx = base + i;
        if (idx < N_) {
            off[idx] = run;
            run += cnt[idx];
            fill[idx] = 0;
        }
    }
    if (tid == 0) off[N_] = E_;
}

#define SEL_DIS_BLOCKS (((T_*R_*N_)+1023)/1024)
__global__ __launch_bounds__(1024) void k_sel() {
    int b = blockIdx.x;
    if (b < T_*C_) {
        topk_body(b);
    } else if (b < T_*C_ + T_) {
        scan_body(b - T_*C_);
    } else {
        int i = (b - T_*C_ - T_)*1024 + threadIdx.x;
        if (i < T_*R_*N_) {
            int d = g_degI[i];
            g_dis[i] = (d > 0) ? (1.f / sqrtf((float)d)) : 0.f;
        }
    }
}

// ================== zt + scatter ==================
#define ZT_BLOCKS ((T_*C_*FO_)/4)
__global__ __launch_bounds__(256) void k_zt_scatter(const float* __restrict__ x,
                                                    const int* __restrict__ ei,
                                                    const int* __restrict__ et) {
    int b = blockIdx.x, tid = threadIdx.x;
    if (b < ZT_BLOCKS) {
        int sub = tid >> 6, l = tid & 63;
        int jct = b*4 + sub;
        int j = jct & 255;
        int cc = jct >> 8;
        int c = cc % C_, t = cc / C_;
        int tc = t*C_ + c;
        int idx = g_tidx[(size_t)tc*FO_ + j];
        float tv = tanhf(g_vals[(size_t)tc*FO_ + j]);
        const float4* xr = (const float4*)(x + ((size_t)t*N_ + idx) * F_);
        float4 v = xr[l];
        v.x *= tv; v.y *= tv; v.z *= tv; v.w *= tv;
        ((float4*)(g_zt + ((size_t)tc*FO_ + j) * F_))[l] = v;
    } else {
        int idx = b - ZT_BLOCKS;
        int t = idx / 1250;
        int e = (idx - t*1250)*256 + tid;
        if (e >= E_) return;
        int row = ei[(size_t)t*2*E_ + e];
        int col = ei[(size_t)t*2*E_ + E_ + e];
        int r   = et[(size_t)t*E_ + e];
        int pos = g_off[t*(N_+1) + row] + atomicAdd(&g_fill[t*N_ + row], 1);
        g_epack[(size_t)t*E_ + pos] = ((uint32_t)col << 2) | (uint32_t)r;
    }
}

// ================== cell bodies ==================
#define CELL_MMA_128(As, Bs)                                                    \
    _Pragma("unroll")                                                           \
    for (int kc = 0; kc < 2; kc++) {                                            \
        int k0 = kc * 8;                                                        \
        uint32_t afr[2][4];                                                     \
        _Pragma("unroll")                                                       \
        for (int mt = 0; mt < 2; mt++) {                                        \
            int mb = wm*32 + mt*16;                                             \
            afr[mt][0] = __float_as_uint(As[k0 + tg    ][mb + grp    ]);        \
            afr[mt][1] = __float_as_uint(As[k0 + tg    ][mb + grp + 8]);        \
            afr[mt][2] = __float_as_uint(As[k0 + tg + 4][mb + grp    ]);        \
            afr[mt][3] = __float_as_uint(As[k0 + tg + 4][mb + grp + 8]);        \
        }                                                                       \
        _Pragma("unroll")                                                       \
        for (int nt = 0; nt < 4; nt++) {                                        \
            int nb = wn*32 + nt*8;                                              \
            uint32_t b0 = __float_as_uint(Bs[k0 + tg    ][nb + grp]);           \
            uint32_t b1 = __float_as_uint(Bs[k0 + tg + 4][nb + grp]);           \
            _Pragma("unroll")                                                   \
            for (int mt = 0; mt < 2; mt++)                                      \
                mma_tf32(d[mt][nt], afr[mt], b0, b1);                           \
        }                                                                       \
    }

__device__ void cell1_body(const float* W, const float* U, const float* B,
                           const float* Z, const float* Qm, float* OUT, int x16) {
    __shared__ float As[16][68], Bs[16][68];
    int tid = threadIdx.x, lane = tid & 31, wid = tid >> 5;
    int wm = wid >> 1, wn = wid & 1;
    int grp = lane >> 2, tg = lane & 3;
    int i0 = (x16 >> 2) * 64, j0 = (x16 & 3) * 64;

    float d[2][4][4];
    #pragma unroll
    for (int mt = 0; mt < 2; mt++)
        #pragma unroll
        for (int nt = 0; nt < 4; nt++)
            #pragma unroll
            for (int q = 0; q < 4; q++) d[mt][nt][q] = 0.f;

    int ar = tid >> 1, ac = (tid & 1) * 8;
    int qk = tid >> 3, qn = (tid & 7) * 8;

    for (int kb = 0; kb < 256; kb += 16) {
        float4 a4 = *(const float4*)(W + (size_t)(i0+ar)*256 + kb + ac);
        float4 a5 = *(const float4*)(W + (size_t)(i0+ar)*256 + kb + ac + 4);
        As[ac  ][ar]=cvt_tf32(a4.x); As[ac+1][ar]=cvt_tf32(a4.y);
        As[ac+2][ar]=cvt_tf32(a4.z); As[ac+3][ar]=cvt_tf32(a4.w);
        As[ac+4][ar]=cvt_tf32(a5.x); As[ac+5][ar]=cvt_tf32(a5.y);
        As[ac+6][ar]=cvt_tf32(a5.z); As[ac+7][ar]=cvt_tf32(a5.w);
        float4 b4 = *(const float4*)(Z + (size_t)(j0+ar)*256 + kb + ac);
        float4 b5 = *(const float4*)(Z + (size_t)(j0+ar)*256 + kb + ac + 4);
        Bs[ac  ][ar]=cvt_tf32(b4.x); Bs[ac+1][ar]=cvt_tf32(b4.y);
        Bs[ac+2][ar]=cvt_tf32(b4.z); Bs[ac+3][ar]=cvt_tf32(b4.w);
        Bs[ac+4][ar]=cvt_tf32(b5.x); Bs[ac+5][ar]=cvt_tf32(b5.y);
        Bs[ac+6][ar]=cvt_tf32(b5.z); Bs[ac+7][ar]=cvt_tf32(b5.w);
        __syncthreads();
        CELL_MMA_128(As, Bs);
        __syncthreads();
    }
    for (int kb = 0; kb < 256; kb += 16) {
        float4 a4 = *(const float4*)(U + (size_t)(i0+ar)*256 + kb + ac);
        float4 a5 = *(const float4*)(U + (size_t)(i0+ar)*256 + kb + ac + 4);
        As[ac  ][ar]=cvt_tf32(a4.x); As[ac+1][ar]=cvt_tf32(a4.y);
        As[ac+2][ar]=cvt_tf32(a4.z); As[ac+3][ar]=cvt_tf32(a4.w);
        As[ac+4][ar]=cvt_tf32(a5.x); As[ac+5][ar]=cvt_tf32(a5.y);
        As[ac+6][ar]=cvt_tf32(a5.z); As[ac+7][ar]=cvt_tf32(a5.w);
        float4 b4 = *(const float4*)(Qm + (size_t)(kb+qk)*256 + j0 + qn);
        float4 b5 = *(const float4*)(Qm + (size_t)(kb+qk)*256 + j0 + qn + 4);
        Bs[qk][qn  ]=cvt_tf32(b4.x); Bs[qk][qn+1]=cvt_tf32(b4.y);
        Bs[qk][qn+2]=cvt_tf32(b4.z); Bs[qk][qn+3]=cvt_tf32(b4.w);
        Bs[qk][qn+4]=cvt_tf32(b5.x); Bs[qk][qn+5]=cvt_tf32(b5.y);
        Bs[qk][qn+6]=cvt_tf32(b5.z); Bs[qk][qn+7]=cvt_tf32(b5.w);
        __syncthreads();
        CELL_MMA_128(As, Bs);
        __syncthreads();
    }

    #pragma unroll
    for (int mt = 0; mt < 2; mt++) {
        #pragma unroll
        for (int nt = 0; nt < 4; nt++) {
            int r0 = i0 + wm*32 + mt*16 + grp;
            int col = j0 + wn*32 + nt*8 + 2*tg;
            float2 bi0 = *(const float2*)(B + (size_t)r0*256 + col);
            *(float2*)&OUT[(size_t)r0*256 + col] =
                make_float2(sigmoidf_(d[mt][nt][0] + bi0.x), sigmoidf_(d[mt][nt][1] + bi0.y));
            int r1 = r0 + 8;
            float2 bi1 = *(const float2*)(B + (size_t)r1*256 + col);
            *(float2*)&OUT[(size_t)r1*256 + col] =
                make_float2(sigmoidf_(d[mt][nt][2] + bi1.x), sigmoidf_(d[mt][nt][3] + bi1.y));
        }
    }
}

#define CELL_MMA_256(As, Bs)                                                    \
    _Pragma("unroll")                                                           \
    for (int kc = 0; kc < 2; kc++) {                                            \
        int k0 = kc * 8;                                                        \
        uint32_t afr[2][4];                                                     \
        _Pragma("unroll")                                                       \
        for (int mt = 0; mt < 2; mt++) {                                        \
            int mb = wm*32 + mt*16;                                             \
            afr[mt][0] = __float_as_uint(As[k0 + tg    ][mb + grp    ]);        \
            afr[mt][1] = __float_as_uint(As[k0 + tg    ][mb + grp + 8]);        \
            afr[mt][2] = __float_as_uint(As[k0 + tg + 4][mb + grp    ]);        \
            afr[mt][3] = __float_as_uint(As[k0 + tg + 4][mb + grp + 8]);        \
        }                                                                       \
        _Pragma("unroll")                                                       \
        for (int nt = 0; nt < 2; nt++) {                                        \
            int nb = wn*16 + nt*8;                                              \
            uint32_t b0 = __float_as_uint(Bs[k0 + tg    ][nb + grp]);           \
            uint32_t b1 = __float_as_uint(Bs[k0 + tg + 4][nb + grp]);           \
            _Pragma("unroll")                                                   \
            for (int mt = 0; mt < 2; mt++)                                      \
                mma_tf32(d[mt][nt], afr[mt], b0, b1);                           \
        }                                                                       \
    }

__device__ void cell2_body(const float* W, const float* U, const float* B,
                           const float* Z, const float* Qin, const float* RST,
                           const float* UPD, float* Qout, float* Qc, int x16) {
    __shared__ float As[16][68], Bs[16][68];
    int tid = threadIdx.x, lane = tid & 31, wid = tid >> 5;
    int wm = wid >> 2, wn = wid & 3;
    int grp = lane >> 2, tg = lane & 3;
    int i0 = (x16 >> 2) * 64, j0 = (x16 & 3) * 64;

    float d[2][2][4];
    #pragma unroll
    for (int mt = 0; mt < 2; mt++)
        #pragma unroll
        for (int nt = 0; nt < 2; nt++)
            #pragma unroll
            for (int q = 0; q < 4; q++) d[mt][nt][q] = 0.f;

    int ar = tid >> 2, ac = (tid & 3) * 4;
    int qk = tid >> 4, qn = (tid & 15) * 4;

    for (int kb = 0; kb < 256; kb += 16) {
        float4 a4 = *(const float4*)(W + (size_t)(i0+ar)*256 + kb + ac);
        As[ac  ][ar]=cvt_tf32(a4.x); As[ac+1][ar]=cvt_tf32(a4.y);
        As[ac+2][ar]=cvt_tf32(a4.z); As[ac+3][ar]=cvt_tf32(a4.w);
        float4 b4 = *(const float4*)(Z + (size_t)(j0+ar)*256 + kb + ac);
        Bs[ac  ][ar]=cvt_tf32(b4.x); Bs[ac+1][ar]=cvt_tf32(b4.y);
        Bs[ac+2][ar]=cvt_tf32(b4.z); Bs[ac+3][ar]=cvt_tf32(b4.w);
        __syncthreads();
        CELL_MMA_256(As, Bs);
        __syncthreads();
    }
    for (int kb = 0; kb < 256; kb += 16) {
        float4 a4 = *(const float4*)(U + (size_t)(i0+ar)*256 + kb + ac);
        As[ac  ][ar]=cvt_tf32(a4.x); As[ac+1][ar]=cvt_tf32(a4.y);
        As[ac+2][ar]=cvt_tf32(a4.z); As[ac+3][ar]=cvt_tf32(a4.w);
        float4 b4 = *(const float4*)(Qin + (size_t)(kb+qk)*256 + j0 + qn);
        float4 r4 = *(const float4*)(RST + (size_t)(kb+qk)*256 + j0 + qn);
        Bs[qk][qn  ]=cvt_tf32(b4.x*r4.x); Bs[qk][qn+1]=cvt_tf32(b4.y*r4.y);
        Bs[qk][qn+2]=cvt_tf32(b4.z*r4.z); Bs[qk][qn+3]=cvt_tf32(b4.w*r4.w);
        __syncthreads();
        CELL_MMA_256(As, Bs);
        __syncthreads();
    }

    #pragma unroll
    for (int mt = 0; mt < 2; mt++) {
        #pragma unroll
        for (int nt = 0; nt < 2; nt++) {
            #pragma unroll
            for (int half = 0; half < 2; half++) {
                int r = i0 + wm*32 + mt*16 + grp + half*8;
                int col = j0 + wn*16 + nt*8 + 2*tg;
                float d0 = d[mt][nt][half*2], d1 = d[mt][nt][half*2 + 1];
                float2 bi = *(const float2*)(B + (size_t)r*256 + col);
                float2 up = *(const float2*)(UPD + (size_t)r*256 + col);
                float2 qi = *(const float2*)(Qin + (size_t)r*256 + col);
                float h0 = tanhf(d0 + bi.x), h1 = tanhf(d1 + bi.y);
                float v0 = (1.f - up.x)*qi.x + up.x*h0;
                float v1 = (1.f - up.y)*qi.y + up.y*h1;
                *(float2*)&Qout[(size_t)r*256 + col] = make_float2(v0, v1);
                *(float2*)&Qc[(size_t)r*256 + col] = make_float2(cvt_tf32(v0), cvt_tf32(v1));
            }
        }
    }
}

__device__ __forceinline__ void cell1_sel(
    int o, int c,
    const float* sWz, const float* sUz, const float* sbz,
    const float* sWr, const float* sUr, const float* sbr,
    const float* rWz, const float* rUz, const float* rbz,
    const float* rWr, const float* rUr, const float* rbr,
    int par, int t, int x16) {
    const float *W, *U, *B;
    if (o == 0) { W = c ? rWz + (c-1)*MAT_ : sWz; U = c ? rUz + (c-1)*MAT_ : sUz; B = c ? rbz + (c-1)*MAT_ : sbz; }
    else        { W = c ? rWr + (c-1)*MAT_ : sWr; U = c ? rUr + (c-1)*MAT_ : sUr; B = c ? rbr + (c-1)*MAT_ : sbr; }
    cell1_body(W, U, B, g_zt + (size_t)(t*C_ + c)*MAT_, g_Q[par] + c*MAT_,
               (o == 0 ? g_upd : g_rst) + c*MAT_, x16);
}

__global__ __launch_bounds__(128) void k_cell1_only(
    const float* sWz, const float* sUz, const float* sbz,
    const float* sWr, const float* sUr, const float* sbr,
    const float* rWz, const float* rUz, const float* rbz,
    const float* rWr, const float* rUr, const float* rbr,
    int par, int t) {
    int u = blockIdx.z;
    cell1_sel(u & 1, u >> 1, sWz, sUz, sbz, sWr, sUr, sbr,
              rWz, rUz, rbz, rWr, rUr, rbr, par, t, blockIdx.x);
}
__global__ __launch_bounds__(256) void k_cell2_only(
    const float* sWh, const float* sUh, const float* sbh,
    const float* rWh, const float* rUh, const float* rbh,
    int par, int t) {
    int c = blockIdx.z;
    const float* W = c ? rWh + (c-1)*MAT_ : sWh;
    const float* U = c ? rUh + (c-1)*MAT_ : sUh;
    const float* B = c ? rbh + (c-1)*MAT_ : sbh;
    cell2_body(W, U, B, g_zt + (size_t)(t*C_ + c)*MAT_,
               g_Q[par] + c*MAT_, g_rst + c*MAT_, g_upd + c*MAT_,
               g_Q[par ^ 1] + c*MAT_, g_Qc + c*MAT_, blockIdx.x);
}

// ================== big GEMM: 128x128 tile, 128 threads, 3-stage cp.async ==================
#define GA_PAD 20
#define GB_PAD 136
#define G_STAGE (128*GA_PAD*4 + 16*GB_PAD*4)
#define G_NSTG  3
#define G_SMEM  (G_NSTG*G_STAGE)

__device__ void gemm_body(float* __restrict__ out, int t, int c, int m0, int n0) {
    const float* Ag = g_xc + (size_t)t*N_*F_;
    const float* Bg = g_Qc + (size_t)c*MAT_;
    float* dst = (c == 0) ? out + (size_t)t*N_*FO_ : g_Y + (size_t)(c-1)*N_*FO_;

    float* smf = (float*)s_dyn;
    uint32_t smb = smem_u32(s_dyn);
    int tid = threadIdx.x, wid = tid >> 5, lane = tid & 31;
    int wm = wid >> 1, wn = wid & 1;
    int grp = lane >> 2, tg = lane & 3;

    float d[4][8][4];
    #pragma unroll
    for (int mt = 0; mt < 4; mt++)
        #pragma unroll
        for (int nt = 0; nt < 8; nt++)
            #pragma unroll
            for (int q = 0; q < 4; q++) d[mt][nt][q] = 0.f;

    auto load_stage = [&](int stg, int kb) {
        uint32_t sa = smb + stg*G_STAGE;
        uint32_t sb = sa + 128*GA_PAD*4;
        #pragma unroll
        for (int i = 0; i < 4; i++) {
            int idx = tid + i*128;
            int row = idx >> 2, ch = idx & 3;
            int gr = m0 + row;
            uint32_t dsta = sa + (uint32_t)(row*GA_PAD + ch*4)*4;
            if (gr < N_) {
                cp_async16(dsta, Ag + (size_t)gr*F_ + kb + ch*4);
            } else {
                *(float4*)(s_dyn + (dsta - smb)) = make_float4(0.f, 0.f, 0.f, 0.f);
            }
        }
        #pragma unroll
        for (int i = 0; i < 4; i++) {
            int idx = tid + i*128;
            int kr = idx >> 5, nch = idx & 31;
            uint32_t dstb = sb + (uint32_t)(kr*GB_PAD + nch*4)*4;
            cp_async16(dstb, Bg + (size_t)(kb + kr)*FO_ + n0 + nch*4);
        }
        CP_COMMIT();
    };

    load_stage(0, 0);
    load_stage(1, 16);

    #pragma unroll 1
    for (int step = 0; step < 16; step++) {
        if (step + 2 < 16) load_stage((step + 2) % G_NSTG, (step + 2) * 16);
        if (step + 2 < 16)      { CP_WAIT(2); }
        else if (step + 1 < 16) { CP_WAIT(1); }
        else                    { CP_WAIT(0); }
        __syncthreads();

        const float* As = smf + (step % G_NSTG) * (G_STAGE/4);
        const float* Bs = As + 128*GA_PAD;

        #pragma unroll
        for (int kc = 0; kc < 2; kc++) {
            int k0 = kc * 8;
            uint32_t a[4][4];
            #pragma unroll
            for (int mt = 0; mt < 4; mt++) {
                int mb = wm*64 + mt*16;
                a[mt][0] = __float_as_uint(As[(mb + grp    )*GA_PAD + k0 + tg    ]);
                a[mt][1] = __float_as_uint(As[(mb + grp + 8)*GA_PAD + k0 + tg    ]);
                a[mt][2] = __float_as_uint(As[(mb + grp    )*GA_PAD + k0 + tg + 4]);
                a[mt][3] = __float_as_uint(As[(mb + grp + 8)*GA_PAD + k0 + tg + 4]);
            }
            #pragma unroll
            for (int nt = 0; nt < 8; nt++) {
                int nb = wn*64 + nt*8;
                uint32_t b0 = __float_as_uint(Bs[(k0 + tg    )*GB_PAD + nb + grp]);
                uint32_t b1 = __float_as_uint(Bs[(k0 + tg + 4)*GB_PAD + nb + grp]);
                #pragma unroll
                for (int mt = 0; mt < 4; mt++)
                    mma_tf32(d[mt][nt], a[mt], b0, b1);
            }
        }
        __syncthreads();
    }

    #pragma unroll
    for (int mt = 0; mt < 4; mt++) {
        #pragma unroll
        for (int nt = 0; nt < 8; nt++) {
            int r0 = m0 + wm*64 + mt*16 + grp;
            int col = n0 + wn*64 + nt*8 + 2*tg;
            if (r0 < N_)
                *(float2*)&dst[(size_t)r0*FO_ + col] = make_float2(d[mt][nt][0], d[mt][nt][1]);
            int r1 = r0 + 8;
            if (r1 < N_)
                *(float2*)&dst[(size_t)r1*FO_ + col] = make_float2(d[mt][nt][2], d[mt][nt][3]);
        }
    }
}

// ================== agg body: 2 warps per row (128 cols each) ==================
__device__ void agg_body(float* __restrict__ out, int t, int item0) {
    int warp = threadIdx.x >> 5, lane = threadIdx.x & 31;
    int item = item0 + warp;                // item = row*2 + half
    int row = item >> 1, half = item & 1;
    if (row >= N_) return;
    const float* dis = g_dis + (size_t)t*R_*N_;
    float disrow[R_];
    #pragma unroll
    for (int r = 0; r < R_; r++) disrow[r] = dis[r*N_ + row];
    float4 acc = make_float4(0.f, 0.f, 0.f, 0.f);
    int beg = g_off[t*(N_+1) + row], end = g_off[t*(N_+1) + row + 1];
    const uint32_t* ep = g_epack + (size_t)t*E_;
    int coff = half*32 + lane;              // float4 index within the 256-col row
    for (int p = beg; p < end; p++) {
        uint32_t pk = ep[p];
        int r = pk & 3;
        int col = pk >> 2;
        float norm = disrow[r] * dis[r*N_ + col];
        if (norm != 0.f) {
            float4 v = ((const float4*)(g_Y + ((size_t)r*N_ + col) * FO_))[coff];
            acc.x += v.x*norm; acc.y += v.y*norm; acc.z += v.z*norm; acc.w += v.w*norm;
        }
    }
    float4* dst = (float4*)(out + (size_t)t*N_*FO_ + (size_t)row*FO_);
    float4 o = dst[coff];
    o.x = fmaxf(o.x + acc.x, 0.f); o.y = fmaxf(o.y + acc.y, 0.f);
    o.z = fmaxf(o.z + acc.z, 0.f); o.w = fmaxf(o.w + acc.w, 0.f);
    dst[coff] = o;
}

// ================== merged per-t kernels (cells at LOW block indices) ==================
__global__ __launch_bounds__(128, 2) void k_gemm_cell1(
    float* __restrict__ out, int t,
    const float* sWz, const float* sUz, const float* sbz,
    const float* sWr, const float* sUr, const float* sbr,
    const float* rWz, const float* rUz, const float* rbz,
    const float* rWr, const float* rUr, const float* rbr,
    int parNext, int tNext, int doCell) {
    int z = blockIdx.z;
    if (z < 2*C_) {
        if (!doCell || blockIdx.x >= 16 || blockIdx.y != 0) return;
        cell1_sel(z & 1, z >> 1, sWz, sUz, sbz, sWr, sUr, sbr,
                  rWz, rUz, rbz, rWr, rUr, rbr, parNext, tNext, blockIdx.x);
    } else {
        gemm_body(out, t, z - 2*C_, blockIdx.x * 128, blockIdx.y * 128);
    }
}

__global__ __launch_bounds__(256) void k_agg_cell2(
    float* __restrict__ out, int t,
    const float* sWh, const float* sUh, const float* sbh,
    const float* rWh, const float* rUh, const float* rbh,
    int parNext, int tNext, int doCell) {
    int x = blockIdx.x;
    if (x < 80) {
        if (!doCell) return;
        int c = x >> 4, x16 = x & 15;
        const float* W = c ? rWh + (c-1)*MAT_ : sWh;
        const float* U = c ? rUh + (c-1)*MAT_ : sUh;
        const float* B = c ? rbh + (c-1)*MAT_ : sbh;
        cell2_body(W, U, B, g_zt + (size_t)(tNext*C_ + c)*MAT_,
                   g_Q[parNext] + c*MAT_, g_rst + c*MAT_, g_upd + c*MAT_,
                   g_Q[parNext ^ 1] + c*MAT_, g_Qc + c*MAT_, x16);
    } else {
        agg_body(out, t, (x - 80) * 8);
    }
}

// ================== launcher ==================
extern "C" void kernel_launch(void* const* d_in, const int* in_sizes, int n_in,
                              void* d_out, int out_size) {
    const float* x       = (const float*)d_in[0];
    const float* mask    = (const float*)d_in[1];
    const float* Wself   = (const float*)d_in[2];
    const float* Wrel    = (const float*)d_in[3];
    const float* sWz     = (const float*)d_in[4];
    const float* sUz     = (const float*)d_in[5];
    const float* sbz     = (const float*)d_in[6];
    const float* sWr     = (const float*)d_in[7];
    const float* sUr     = (const float*)d_in[8];
    const float* sbr     = (const float*)d_in[9];
    const float* sWh     = (const float*)d_in[10];
    const float* sUh     = (const float*)d_in[11];
    const float* sbh     = (const float*)d_in[12];
    const float* s_sc    = (const float*)d_in[13];
    const float* rWz     = (const float*)d_in[14];
    const float* rUz     = (const float*)d_in[15];
    const float* rbz     = (const float*)d_in[16];
    const float* rWr     = (const float*)d_in[17];
    const float* rUr     = (const float*)d_in[18];
    const float* rbr     = (const float*)d_in[19];
    const float* rWh     = (const float*)d_in[20];
    const float* rUh     = (const float*)d_in[21];
    const float* rbh     = (const float*)d_in[22];
    const float* r_sc    = (const float*)d_in[23];
    const int*   ei      = (const int*)d_in[24];
    const int*   et      = (const int*)d_in[25];
    float* out = (float*)d_out;

    static bool attr_set = false;
    if (!attr_set) {
        cudaFuncSetAttribute(k_sel, cudaFuncAttributeMaxDynamicSharedMemorySize,
                             N_ * (int)sizeof(uint32_t));
        cudaFuncSetAttribute(k_gemm_cell1, cudaFuncAttributeMaxDynamicSharedMemorySize,
                             G_SMEM);
        attr_set = true;
    }

    // preamble (R9 structure)
    k_prep<<<PB_TOTAL, 256>>>(Wself, Wrel, x, s_sc, r_sc);
    k_scores_edge<<<7500 + 3750, 256>>>(x, mask, s_sc, r_sc, ei, et);
    k_sel<<<T_*C_ + T_ + SEL_DIS_BLOCKS, 1024, N_ * sizeof(uint32_t)>>>();
    k_zt_scatter<<<ZT_BLOCKS + 3750, 256>>>(x, ei, et);

    // t = 0 cells
    k_cell1_only<<<dim3(16, 1, 2*C_), 128>>>(sWz, sUz, sbz, sWr, sUr, sbr,
                                             rWz, rUz, rbz, rWr, rUr, rbr, 0, 0);
    k_cell2_only<<<dim3(16, 1, C_), 256>>>(sWh, sUh, sbh, rWh, rUh, rbh, 0, 0);

    // pipelined recurrence; agg now 2 warps/row -> 5000 agg blocks
    for (int t = 0; t < T_; t++) {
        int doCell = (t + 1 < T_) ? 1 : 0;
        int parN = (t + 1) & 1;
        k_gemm_cell1<<<dim3((N_ + 127)/128, 2, 2*C_ + C_), 128, G_SMEM>>>(
            out, t, sWz, sUz, sbz, sWr, sUr, sbr,
            rWz, rUz, rbz, rWr, rUr, rbr, parN, t + 1, doCell);
        k_agg_cell2<<<80 + 5000, 256>>>(
            out, t, sWh, sUh, sbh, rWh, rUh, rbh, parN, t + 1, doCell);
    }
}

// round 14
// speedup vs baseline: 1.0308x; 1.0308x over previous
#include <cuda_runtime.h>
#include <math.h>
#include <stdint.h>

#define T_ 3
#define N_ 20000
#define F_ 256
#define FO_ 256
#define E_ 320000
#define R_ 4
#define C_ 5
#define MAT_ (F_*FO_)

// ---------------- scratch ----------------
__device__ float g_scores[T_*C_*N_];
__device__ float g_vals  [T_*C_*FO_];
__device__ int   g_tidx  [T_*C_*FO_];
__device__ float g_zt    [T_*C_*MAT_];
__device__ float g_upd   [C_*MAT_];
__device__ float g_rst   [C_*MAT_];
__device__ float g_Q  [2][C_*MAT_];
__device__ float g_Qc    [C_*MAT_];
__device__ float g_xc    [T_*N_*F_];
__device__ float g_Y     [R_*N_*FO_];
__device__ int   g_degI  [T_*R_*N_];   // zero at entry (self-cleaned at end of each invocation)
__device__ float g_dis   [T_*R_*N_];
__device__ int      g_cnt [T_*N_];     // zero at entry (self-cleaned)
__device__ int      g_off [T_*(N_+1)];
__device__ int      g_fill[T_*N_];
__device__ uint32_t g_epack[T_*E_];

extern __shared__ unsigned char s_dyn[];

__device__ __forceinline__ uint32_t f2key(float f) {
    uint32_t u = __float_as_uint(f);
    return (u & 0x80000000u) ? ~u : (u | 0x80000000u);
}
__device__ __forceinline__ float key2f(uint32_t k) {
    return (k & 0x80000000u) ? __uint_as_float(k & 0x7FFFFFFFu) : __uint_as_float(~k);
}
__device__ __forceinline__ float cvt_tf32(float f) {
    uint32_t r;
    asm("cvt.rna.tf32.f32 %0, %1;" : "=r"(r) : "f"(f));
    return __uint_as_float(r);
}
__device__ __forceinline__ float sigmoidf_(float v) { return 1.f / (1.f + expf(-v)); }

__device__ __forceinline__ void mma_tf32(float* d, const uint32_t* a, uint32_t b0, uint32_t b1) {
    asm volatile(
        "mma.sync.aligned.m16n8k8.row.col.f32.tf32.tf32.f32 "
        "{%0,%1,%2,%3}, {%4,%5,%6,%7}, {%8,%9}, {%0,%1,%2,%3};"
        : "+f"(d[0]), "+f"(d[1]), "+f"(d[2]), "+f"(d[3])
        : "r"(a[0]), "r"(a[1]), "r"(a[2]), "r"(a[3]), "r"(b0), "r"(b1));
}
__device__ __forceinline__ uint32_t smem_u32(const void* p) {
    uint32_t a;
    asm("{ .reg .u64 t; cvta.to.shared.u64 t, %1; cvt.u32.u64 %0, t; }" : "=r"(a) : "l"(p));
    return a;
}
__device__ __forceinline__ void cp_async16(uint32_t dst, const void* src) {
    asm volatile("cp.async.ca.shared.global [%0], [%1], 16;" :: "r"(dst), "l"(src) : "memory");
}
#define CP_COMMIT()  asm volatile("cp.async.commit_group;" ::: "memory")
#define CP_WAIT(n)   asm volatile("cp.async.wait_group %0;" :: "n"(n) : "memory")

// ================== L1: scores + edge count + initQ + xcvt (all independent) ==================
#define PA_SCORE (T_*2500)            // 7500
#define PA_CNT   (T_*1250)            // 3750
#define PA_INIT  ((C_*MAT_)/256)      // 1280
#define PA_XCVT  ((T_*N_*F_/4)/256)   // 15000
#define PA_TOTAL (PA_SCORE + PA_CNT + PA_INIT + PA_XCVT)

__global__ __launch_bounds__(256) void k_prep_all(const float* __restrict__ Wself,
                                                  const float* __restrict__ Wrel,
                                                  const float* __restrict__ x,
                                                  const float* __restrict__ mask,
                                                  const float* __restrict__ s_sc,
                                                  const float* __restrict__ r_sc,
                                                  const int* __restrict__ ei,
                                                  const int* __restrict__ et) {
    int b = blockIdx.x, tid = threadIdx.x;
    if (b < PA_SCORE) {
        int t = b / 2500, blk = b - t*2500;
        __shared__ float sc[C_][F_];
        __shared__ float sden[C_];
        for (int i = tid; i < C_*F_; i += 256) {
            int c = i / F_, f = i - c*F_;
            sc[c][f] = (c == 0) ? s_sc[f] : r_sc[(c-1)*F_ + f];
        }
        __syncthreads();
        int warp = tid >> 5, lane = tid & 31;
        if (warp < C_) {
            float s = 0.f;
            #pragma unroll
            for (int q = 0; q < 8; q++) { float v = sc[warp][lane + q*32]; s += v*v; }
            for (int o = 16; o > 0; o >>= 1) s += __shfl_down_sync(0xffffffffu, s, o);
            if (lane == 0) sden[warp] = sqrtf(s) + 1e-8f;
        }
        __syncthreads();
        int n = blk * 8 + warp;
        if (n >= N_) return;
        const float4* xr = (const float4*)(x + ((size_t)t*N_ + n) * F_);
        float acc[C_] = {0.f, 0.f, 0.f, 0.f, 0.f};
        #pragma unroll
        for (int q = 0; q < 2; q++) {
            float4 xv = xr[lane + q*32];
            int e0 = (lane + q*32) * 4;
            #pragma unroll
            for (int c = 0; c < C_; c++) {
                acc[c] += xv.x * sc[c][e0]   + xv.y * sc[c][e0+1]
                        + xv.z * sc[c][e0+2] + xv.w * sc[c][e0+3];
            }
        }
        #pragma unroll
        for (int c = 0; c < C_; c++) {
            float v = acc[c];
            for (int o = 16; o > 0; o >>= 1) v += __shfl_down_sync(0xffffffffu, v, o);
            if (lane == 0)
                g_scores[(size_t)(t*C_ + c)*N_ + n] = v / sden[c] + mask[(size_t)t*N_ + n];
        }
    } else if (b < PA_SCORE + PA_CNT) {
        int idx = b - PA_SCORE;
        int t = idx / 1250;
        int e = (idx - t*1250)*256 + tid;
        if (e >= E_) return;
        int row = ei[(size_t)t*2*E_ + e];
        int r   = et[(size_t)t*E_ + e];
        atomicAdd(&g_degI[(t*R_ + r)*N_ + row], 1);
        atomicAdd(&g_cnt[t*N_ + row], 1);
    } else if (b < PA_SCORE + PA_CNT + PA_INIT) {
        int i = (b - PA_SCORE - PA_CNT)*256 + tid;
        int c = i / MAT_, off = i - c*MAT_;
        g_Q[0][i] = (c == 0) ? Wself[off] : Wrel[(c-1)*MAT_ + off];
    } else {
        int i = (b - PA_SCORE - PA_CNT - PA_INIT)*256 + tid;
        float4 v = ((const float4*)x)[i];
        v.x = cvt_tf32(v.x); v.y = cvt_tf32(v.y);
        v.z = cvt_tf32(v.z); v.w = cvt_tf32(v.w);
        ((float4*)g_xc)[i] = v;
    }
}

// ================== L2: topk + scan + dis ==================
__device__ void topk_body(int tc) {
    uint32_t* s_keys = (uint32_t*)s_dyn;
    __shared__ int      hist[256];
    __shared__ int      sfx[256];
    __shared__ uint32_t selKey[256];
    __shared__ int      selIdx[256];
    __shared__ uint32_t s_prefix;
    __shared__ int      s_remaining, s_eqCount, s_idxTh, s_cnt;

    int tid = threadIdx.x;
    const float* sc = g_scores + (size_t)tc * N_;

    if (tid < 256) hist[tid] = 0;
    if (tid == 0) { s_prefix = 0u; s_remaining = FO_; s_idxTh = 0x7FFFFFFF; s_eqCount = FO_; }
    __syncthreads();

    for (int i = tid; i < N_; i += 1024) {
        uint32_t k = f2key(sc[i]);
        s_keys[i] = k;
        atomicAdd(&hist[k >> 24], 1);
    }
    __syncthreads();

    #pragma unroll
    for (int pass = 3; pass >= 0; pass--) {
        int shift = pass * 8;
        if (pass < 3) {
            if (tid < 256) hist[tid] = 0;
            __syncthreads();
            uint32_t prefix = s_prefix;
            uint32_t pmask = 0xFFFFFFFFu << (shift + 8);
            for (int i = tid; i < N_; i += 1024) {
                uint32_t k = s_keys[i];
                if ((k & pmask) == (prefix & pmask))
                    atomicAdd(&hist[(k >> shift) & 0xFF], 1);
            }
            __syncthreads();
        }
        if (tid < 256) sfx[tid] = hist[tid];
        __syncthreads();
        #pragma unroll
        for (int o = 1; o < 256; o <<= 1) {
            int v = 0;
            if (tid < 256) v = sfx[tid] + ((tid + o < 256) ? sfx[tid + o] : 0);
            __syncthreads();
            if (tid < 256) sfx[tid] = v;
            __syncthreads();
        }
        int rem = s_remaining;
        __syncthreads();
        if (tid < 256) {
            int s  = sfx[tid];
            int sn = (tid < 255) ? sfx[tid + 1] : 0;
            if (s >= rem && sn < rem) {
                s_prefix |= ((uint32_t)tid) << shift;
                s_remaining = rem - sn;
                if (pass == 0) s_eqCount = hist[tid];
            }
        }
        __syncthreads();
    }
    uint32_t kth = s_prefix;
    int need = s_remaining;

    if (need < s_eqCount) {
        if (tid == 0) { s_prefix = 0u; s_remaining = need; }
        __syncthreads();
        #pragma unroll
        for (int pass = 1; pass >= 0; pass--) {
            int shift = pass * 8;
            if (tid < 256) hist[tid] = 0;
            __syncthreads();
            uint32_t prefixI = s_prefix;
            for (int i = tid; i < N_; i += 1024) {
                if (s_keys[i] == kth) {
                    if (pass == 1 || (((uint32_t)i >> 8) & 0xFF) == ((prefixI >> 8) & 0xFF))
                        atomicAdd(&hist[((uint32_t)i >> shift) & 0xFF], 1);
                }
            }
            __syncthreads();
            if (tid == 0) {
                int rem = s_remaining;
                uint32_t pfx = s_prefix;
                for (int bb = 0; bb < 256; bb++) {
                    int cnt = hist[bb];
                    if (cnt >= rem) { pfx |= ((uint32_t)bb) << shift; break; }
                    rem -= cnt;
                }
                s_remaining = rem;
                s_prefix = pfx;
            }
            __syncthreads();
        }
        if (tid == 0) s_idxTh = (int)s_prefix;
    }
    if (tid == 0) s_cnt = 0;
    __syncthreads();
    int idxTh = s_idxTh;

    for (int i = tid; i < N_; i += 1024) {
        uint32_t k = s_keys[i];
        if (k > kth || (k == kth && i <= idxTh)) {
            int p = atomicAdd(&s_cnt, 1);
            selKey[p] = k;
            selIdx[p] = i;
        }
    }
    __syncthreads();

    for (int k = 2; k <= 256; k <<= 1) {
        for (int j = k >> 1; j > 0; j >>= 1) {
            if (tid < 256) {
                int ixj = tid ^ j;
                if (ixj > tid) {
                    bool desc = ((tid & k) == 0);
                    uint32_t ka = selKey[tid], kb = selKey[ixj];
                    int ia = selIdx[tid], ib = selIdx[ixj];
                    bool aGreater = (ka > kb) || (ka == kb && ia < ib);
                    bool doswap = desc ? !aGreater : aGreater;
                    if (doswap) {
                        selKey[tid] = kb; selKey[ixj] = ka;
                        selIdx[tid] = ib; selIdx[ixj] = ia;
                    }
                }
            }
            __syncthreads();
        }
    }

    if (tid < 256) {
        g_vals[(size_t)tc*FO_ + tid] = key2f(selKey[tid]);
        g_tidx[(size_t)tc*FO_ + tid] = selIdx[tid];
    }
}

__device__ void scan_body(int t) {
    __shared__ int part[1024];
    const int* cnt = g_cnt + t*N_;
    int* off = g_off + t*(N_+1);
    int* fill = g_fill + t*N_;
    int tid = threadIdx.x;
    const int CH = (N_ + 1023) / 1024;
    int base = tid * CH;
    int s = 0;
    for (int i = 0; i < CH; i++) {
        int idx = base + i;
        if (idx < N_) s += cnt[idx];
    }
    part[tid] = s;
    __syncthreads();
    for (int o = 1; o < 1024; o <<= 1) {
        int v = (tid >= o) ? part[tid - o] : 0;
        __syncthreads();
        part[tid] += v;
        __syncthreads();
    }
    int run = (tid == 0) ? 0 : part[tid - 1];
    for (int i = 0; i < CH; i++) {
        int idx = base + i;
        if (idx < N_) {
            off[idx] = run;
            run += cnt[idx];
            fill[idx] = 0;
        }
    }
    if (tid == 0) off[N_] = E_;
}

#define SEL_DIS_BLOCKS (((T_*R_*N_)+1023)/1024)
__global__ __launch_bounds__(1024) void k_sel() {
    int b = blockIdx.x;
    if (b < T_*C_) {
        topk_body(b);
    } else if (b < T_*C_ + T_) {
        scan_body(b - T_*C_);
    } else {
        int i = (b - T_*C_ - T_)*1024 + threadIdx.x;
        if (i < T_*R_*N_) {
            int d = g_degI[i];
            g_dis[i] = (d > 0) ? (1.f / sqrtf((float)d)) : 0.f;
        }
    }
}

// ================== L3: zt + scatter + re-zero counters (self-clean) ==================
#define ZT_BLOCKS ((T_*C_*FO_)/4)
#define RZ_BLOCKS (((T_*R_*N_)+255)/256)
__global__ __launch_bounds__(256) void k_zt_scatter(const float* __restrict__ x,
                                                    const int* __restrict__ ei,
                                                    const int* __restrict__ et) {
    int b = blockIdx.x, tid = threadIdx.x;
    if (b < ZT_BLOCKS) {
        int sub = tid >> 6, l = tid & 63;
        int jct = b*4 + sub;
        int j = jct & 255;
        int cc = jct >> 8;
        int c = cc % C_, t = cc / C_;
        int tc = t*C_ + c;
        int idx = g_tidx[(size_t)tc*FO_ + j];
        float tv = tanhf(g_vals[(size_t)tc*FO_ + j]);
        const float4* xr = (const float4*)(x + ((size_t)t*N_ + idx) * F_);
        float4 v = xr[l];
        v.x *= tv; v.y *= tv; v.z *= tv; v.w *= tv;
        ((float4*)(g_zt + ((size_t)tc*FO_ + j) * F_))[l] = v;
    } else if (b < ZT_BLOCKS + T_*1250) {
        int idx = b - ZT_BLOCKS;
        int t = idx / 1250;
        int e = (idx - t*1250)*256 + tid;
        if (e >= E_) return;
        int row = ei[(size_t)t*2*E_ + e];
        int col = ei[(size_t)t*2*E_ + E_ + e];
        int r   = et[(size_t)t*E_ + e];
        int pos = g_off[t*(N_+1) + row] + atomicAdd(&g_fill[t*N_ + row], 1);
        g_epack[(size_t)t*E_ + pos] = ((uint32_t)col << 2) | (uint32_t)r;
    } else {
        // re-zero counters for the next invocation (dis/off already extracted)
        int i = (b - ZT_BLOCKS - T_*1250)*256 + tid;
        if (i < T_*R_*N_) g_degI[i] = 0;
        if (i < T_*N_) g_cnt[i] = 0;
    }
}

// ================== cell bodies ==================
#define CELL_MMA_128(As, Bs)                                                    \
    _Pragma("unroll")                                                           \
    for (int kc = 0; kc < 2; kc++) {                                            \
        int k0 = kc * 8;                                                        \
        uint32_t afr[2][4];                                                     \
        _Pragma("unroll")                                                       \
        for (int mt = 0; mt < 2; mt++) {                                        \
            int mb = wm*32 + mt*16;                                             \
            afr[mt][0] = __float_as_uint(As[k0 + tg    ][mb + grp    ]);        \
            afr[mt][1] = __float_as_uint(As[k0 + tg    ][mb + grp + 8]);        \
            afr[mt][2] = __float_as_uint(As[k0 + tg + 4][mb + grp    ]);        \
            afr[mt][3] = __float_as_uint(As[k0 + tg + 4][mb + grp + 8]);        \
        }                                                                       \
        _Pragma("unroll")                                                       \
        for (int nt = 0; nt < 4; nt++) {                                        \
            int nb = wn*32 + nt*8;                                              \
            uint32_t b0 = __float_as_uint(Bs[k0 + tg    ][nb + grp]);           \
            uint32_t b1 = __float_as_uint(Bs[k0 + tg + 4][nb + grp]);           \
            _Pragma("unroll")                                                   \
            for (int mt = 0; mt < 2; mt++)                                      \
                mma_tf32(d[mt][nt], afr[mt], b0, b1);                           \
        }                                                                       \
    }

__device__ void cell1_body(const float* W, const float* U, const float* B,
                           const float* Z, const float* Qm, float* OUT, int x16) {
    __shared__ float As[16][68], Bs[16][68];
    int tid = threadIdx.x, lane = tid & 31, wid = tid >> 5;
    int wm = wid >> 1, wn = wid & 1;
    int grp = lane >> 2, tg = lane & 3;
    int i0 = (x16 >> 2) * 64, j0 = (x16 & 3) * 64;

    float d[2][4][4];
    #pragma unroll
    for (int mt = 0; mt < 2; mt++)
        #pragma unroll
        for (int nt = 0; nt < 4; nt++)
            #pragma unroll
            for (int q = 0; q < 4; q++) d[mt][nt][q] = 0.f;

    int ar = tid >> 1, ac = (tid & 1) * 8;
    int qk = tid >> 3, qn = (tid & 7) * 8;

    for (int kb = 0; kb < 256; kb += 16) {
        float4 a4 = *(const float4*)(W + (size_t)(i0+ar)*256 + kb + ac);
        float4 a5 = *(const float4*)(W + (size_t)(i0+ar)*256 + kb + ac + 4);
        As[ac  ][ar]=cvt_tf32(a4.x); As[ac+1][ar]=cvt_tf32(a4.y);
        As[ac+2][ar]=cvt_tf32(a4.z); As[ac+3][ar]=cvt_tf32(a4.w);
        As[ac+4][ar]=cvt_tf32(a5.x); As[ac+5][ar]=cvt_tf32(a5.y);
        As[ac+6][ar]=cvt_tf32(a5.z); As[ac+7][ar]=cvt_tf32(a5.w);
        float4 b4 = *(const float4*)(Z + (size_t)(j0+ar)*256 + kb + ac);
        float4 b5 = *(const float4*)(Z + (size_t)(j0+ar)*256 + kb + ac + 4);
        Bs[ac  ][ar]=cvt_tf32(b4.x); Bs[ac+1][ar]=cvt_tf32(b4.y);
        Bs[ac+2][ar]=cvt_tf32(b4.z); Bs[ac+3][ar]=cvt_tf32(b4.w);
        Bs[ac+4][ar]=cvt_tf32(b5.x); Bs[ac+5][ar]=cvt_tf32(b5.y);
        Bs[ac+6][ar]=cvt_tf32(b5.z); Bs[ac+7][ar]=cvt_tf32(b5.w);
        __syncthreads();
        CELL_MMA_128(As, Bs);
        __syncthreads();
    }
    for (int kb = 0; kb < 256; kb += 16) {
        float4 a4 = *(const float4*)(U + (size_t)(i0+ar)*256 + kb + ac);
        float4 a5 = *(const float4*)(U + (size_t)(i0+ar)*256 + kb + ac + 4);
        As[ac  ][ar]=cvt_tf32(a4.x); As[ac+1][ar]=cvt_tf32(a4.y);
        As[ac+2][ar]=cvt_tf32(a4.z); As[ac+3][ar]=cvt_tf32(a4.w);
        As[ac+4][ar]=cvt_tf32(a5.x); As[ac+5][ar]=cvt_tf32(a5.y);
        As[ac+6][ar]=cvt_tf32(a5.z); As[ac+7][ar]=cvt_tf32(a5.w);
        float4 b4 = *(const float4*)(Qm + (size_t)(kb+qk)*256 + j0 + qn);
        float4 b5 = *(const float4*)(Qm + (size_t)(kb+qk)*256 + j0 + qn + 4);
        Bs[qk][qn  ]=cvt_tf32(b4.x); Bs[qk][qn+1]=cvt_tf32(b4.y);
        Bs[qk][qn+2]=cvt_tf32(b4.z); Bs[qk][qn+3]=cvt_tf32(b4.w);
        Bs[qk][qn+4]=cvt_tf32(b5.x); Bs[qk][qn+5]=cvt_tf32(b5.y);
        Bs[qk][qn+6]=cvt_tf32(b5.z); Bs[qk][qn+7]=cvt_tf32(b5.w);
        __syncthreads();
        CELL_MMA_128(As, Bs);
        __syncthreads();
    }

    #pragma unroll
    for (int mt = 0; mt < 2; mt++) {
        #pragma unroll
        for (int nt = 0; nt < 4; nt++) {
            int r0 = i0 + wm*32 + mt*16 + grp;
            int col = j0 + wn*32 + nt*8 + 2*tg;
            float2 bi0 = *(const float2*)(B + (size_t)r0*256 + col);
            *(float2*)&OUT[(size_t)r0*256 + col] =
                make_float2(sigmoidf_(d[mt][nt][0] + bi0.x), sigmoidf_(d[mt][nt][1] + bi0.y));
            int r1 = r0 + 8;
            float2 bi1 = *(const float2*)(B + (size_t)r1*256 + col);
            *(float2*)&OUT[(size_t)r1*256 + col] =
                make_float2(sigmoidf_(d[mt][nt][2] + bi1.x), sigmoidf_(d[mt][nt][3] + bi1.y));
        }
    }
}

#define CELL_MMA_256(As, Bs)                                                    \
    _Pragma("unroll")                                                           \
    for (int kc = 0; kc < 2; kc++) {                                            \
        int k0 = kc * 8;                                                        \
        uint32_t afr[2][4];                                                     \
        _Pragma("unroll")                                                       \
        for (int mt = 0; mt < 2; mt++) {                                        \
            int mb = wm*32 + mt*16;                                             \
            afr[mt][0] = __float_as_uint(As[k0 + tg    ][mb + grp    ]);        \
            afr[mt][1] = __float_as_uint(As[k0 + tg    ][mb + grp + 8]);        \
            afr[mt][2] = __float_as_uint(As[k0 + tg + 4][mb + grp    ]);        \
            afr[mt][3] = __float_as_uint(As[k0 + tg + 4][mb + grp + 8]);        \
        }                                                                       \
        _Pragma("unroll")                                                       \
        for (int nt = 0; nt < 2; nt++) {                                        \
            int nb = wn*16 + nt*8;                                              \
            uint32_t b0 = __float_as_uint(Bs[k0 + tg    ][nb + grp]);           \
            uint32_t b1 = __float_as_uint(Bs[k0 + tg + 4][nb + grp]);           \
            _Pragma("unroll")                                                   \
            for (int mt = 0; mt < 2; mt++)                                      \
                mma_tf32(d[mt][nt], afr[mt], b0, b1);                           \
        }                                                                       \
    }

__device__ void cell2_body(const float* W, const float* U, const float* B,
                           const float* Z, const float* Qin, const float* RST,
                           const float* UPD, float* Qout, float* Qc, int x16) {
    __shared__ float As[16][68], Bs[16][68];
    int tid = threadIdx.x, lane = tid & 31, wid = tid >> 5;
    int wm = wid >> 2, wn = wid & 3;
    int grp = lane >> 2, tg = lane & 3;
    int i0 = (x16 >> 2) * 64, j0 = (x16 & 3) * 64;

    float d[2][2][4];
    #pragma unroll
    for (int mt = 0; mt < 2; mt++)
        #pragma unroll
        for (int nt = 0; nt < 2; nt++)
            #pragma unroll
            for (int q = 0; q < 4; q++) d[mt][nt][q] = 0.f;

    int ar = tid >> 2, ac = (tid & 3) * 4;
    int qk = tid >> 4, qn = (tid & 15) * 4;

    for (int kb = 0; kb < 256; kb += 16) {
        float4 a4 = *(const float4*)(W + (size_t)(i0+ar)*256 + kb + ac);
        As[ac  ][ar]=cvt_tf32(a4.x); As[ac+1][ar]=cvt_tf32(a4.y);
        As[ac+2][ar]=cvt_tf32(a4.z); As[ac+3][ar]=cvt_tf32(a4.w);
        float4 b4 = *(const float4*)(Z + (size_t)(j0+ar)*256 + kb + ac);
        Bs[ac  ][ar]=cvt_tf32(b4.x); Bs[ac+1][ar]=cvt_tf32(b4.y);
        Bs[ac+2][ar]=cvt_tf32(b4.z); Bs[ac+3][ar]=cvt_tf32(b4.w);
        __syncthreads();
        CELL_MMA_256(As, Bs);
        __syncthreads();
    }
    for (int kb = 0; kb < 256; kb += 16) {
        float4 a4 = *(const float4*)(U + (size_t)(i0+ar)*256 + kb + ac);
        As[ac  ][ar]=cvt_tf32(a4.x); As[ac+1][ar]=cvt_tf32(a4.y);
        As[ac+2][ar]=cvt_tf32(a4.z); As[ac+3][ar]=cvt_tf32(a4.w);
        float4 b4 = *(const float4*)(Qin + (size_t)(kb+qk)*256 + j0 + qn);
        float4 r4 = *(const float4*)(RST + (size_t)(kb+qk)*256 + j0 + qn);
        Bs[qk][qn  ]=cvt_tf32(b4.x*r4.x); Bs[qk][qn+1]=cvt_tf32(b4.y*r4.y);
        Bs[qk][qn+2]=cvt_tf32(b4.z*r4.z); Bs[qk][qn+3]=cvt_tf32(b4.w*r4.w);
        __syncthreads();
        CELL_MMA_256(As, Bs);
        __syncthreads();
    }

    #pragma unroll
    for (int mt = 0; mt < 2; mt++) {
        #pragma unroll
        for (int nt = 0; nt < 2; nt++) {
            #pragma unroll
            for (int half = 0; half < 2; half++) {
                int r = i0 + wm*32 + mt*16 + grp + half*8;
                int col = j0 + wn*16 + nt*8 + 2*tg;
                float d0 = d[mt][nt][half*2], d1 = d[mt][nt][half*2 + 1];
                float2 bi = *(const float2*)(B + (size_t)r*256 + col);
                float2 up = *(const float2*)(UPD + (size_t)r*256 + col);
                float2 qi = *(const float2*)(Qin + (size_t)r*256 + col);
                float h0 = tanhf(d0 + bi.x), h1 = tanhf(d1 + bi.y);
                float v0 = (1.f - up.x)*qi.x + up.x*h0;
                float v1 = (1.f - up.y)*qi.y + up.y*h1;
                *(float2*)&Qout[(size_t)r*256 + col] = make_float2(v0, v1);
                *(float2*)&Qc[(size_t)r*256 + col] = make_float2(cvt_tf32(v0), cvt_tf32(v1));
            }
        }
    }
}

__device__ __forceinline__ void cell1_sel(
    int o, int c,
    const float* sWz, const float* sUz, const float* sbz,
    const float* sWr, const float* sUr, const float* sbr,
    const float* rWz, const float* rUz, const float* rbz,
    const float* rWr, const float* rUr, const float* rbr,
    int par, int t, int x16) {
    const float *W, *U, *B;
    if (o == 0) { W = c ? rWz + (c-1)*MAT_ : sWz; U = c ? rUz + (c-1)*MAT_ : sUz; B = c ? rbz + (c-1)*MAT_ : sbz; }
    else        { W = c ? rWr + (c-1)*MAT_ : sWr; U = c ? rUr + (c-1)*MAT_ : sUr; B = c ? rbr + (c-1)*MAT_ : sbr; }
    cell1_body(W, U, B, g_zt + (size_t)(t*C_ + c)*MAT_, g_Q[par] + c*MAT_,
               (o == 0 ? g_upd : g_rst) + c*MAT_, x16);
}

__global__ __launch_bounds__(128) void k_cell1_only(
    const float* sWz, const float* sUz, const float* sbz,
    const float* sWr, const float* sUr, const float* sbr,
    const float* rWz, const float* rUz, const float* rbz,
    const float* rWr, const float* rUr, const float* rbr,
    int par, int t) {
    int u = blockIdx.z;
    cell1_sel(u & 1, u >> 1, sWz, sUz, sbz, sWr, sUr, sbr,
              rWz, rUz, rbz, rWr, rUr, rbr, par, t, blockIdx.x);
}
__global__ __launch_bounds__(256) void k_cell2_only(
    const float* sWh, const float* sUh, const float* sbh,
    const float* rWh, const float* rUh, const float* rbh,
    int par, int t) {
    int c = blockIdx.z;
    const float* W = c ? rWh + (c-1)*MAT_ : sWh;
    const float* U = c ? rUh + (c-1)*MAT_ : sUh;
    const float* B = c ? rbh + (c-1)*MAT_ : sbh;
    cell2_body(W, U, B, g_zt + (size_t)(t*C_ + c)*MAT_,
               g_Q[par] + c*MAT_, g_rst + c*MAT_, g_upd + c*MAT_,
               g_Q[par ^ 1] + c*MAT_, g_Qc + c*MAT_, blockIdx.x);
}

// ================== big GEMM: 128x128 tile, 128 threads, 3-stage cp.async ==================
#define GA_PAD 20
#define GB_PAD 136
#define G_STAGE (128*GA_PAD*4 + 16*GB_PAD*4)
#define G_NSTG  3
#define G_SMEM  (G_NSTG*G_STAGE)

__device__ void gemm_body(float* __restrict__ out, int t, int c, int m0, int n0) {
    const float* Ag = g_xc + (size_t)t*N_*F_;
    const float* Bg = g_Qc + (size_t)c*MAT_;
    float* dst = (c == 0) ? out + (size_t)t*N_*FO_ : g_Y + (size_t)(c-1)*N_*FO_;

    float* smf = (float*)s_dyn;
    uint32_t smb = smem_u32(s_dyn);
    int tid = threadIdx.x, wid = tid >> 5, lane = tid & 31;
    int wm = wid >> 1, wn = wid & 1;
    int grp = lane >> 2, tg = lane & 3;

    float d[4][8][4];
    #pragma unroll
    for (int mt = 0; mt < 4; mt++)
        #pragma unroll
        for (int nt = 0; nt < 8; nt++)
            #pragma unroll
            for (int q = 0; q < 4; q++) d[mt][nt][q] = 0.f;

    auto load_stage = [&](int stg, int kb) {
        uint32_t sa = smb + stg*G_STAGE;
        uint32_t sb = sa + 128*GA_PAD*4;
        #pragma unroll
        for (int i = 0; i < 4; i++) {
            int idx = tid + i*128;
            int row = idx >> 2, ch = idx & 3;
            int gr = m0 + row;
            uint32_t dsta = sa + (uint32_t)(row*GA_PAD + ch*4)*4;
            if (gr < N_) {
                cp_async16(dsta, Ag + (size_t)gr*F_ + kb + ch*4);
            } else {
                *(float4*)(s_dyn + (dsta - smb)) = make_float4(0.f, 0.f, 0.f, 0.f);
            }
        }
        #pragma unroll
        for (int i = 0; i < 4; i++) {
            int idx = tid + i*128;
            int kr = idx >> 5, nch = idx & 31;
            uint32_t dstb = sb + (uint32_t)(kr*GB_PAD + nch*4)*4;
            cp_async16(dstb, Bg + (size_t)(kb + kr)*FO_ + n0 + nch*4);
        }
        CP_COMMIT();
    };

    load_stage(0, 0);
    load_stage(1, 16);

    #pragma unroll 1
    for (int step = 0; step < 16; step++) {
        if (step + 2 < 16) load_stage((step + 2) % G_NSTG, (step + 2) * 16);
        if (step + 2 < 16)      { CP_WAIT(2); }
        else if (step + 1 < 16) { CP_WAIT(1); }
        else                    { CP_WAIT(0); }
        __syncthreads();

        const float* As = smf + (step % G_NSTG) * (G_STAGE/4);
        const float* Bs = As + 128*GA_PAD;

        #pragma unroll
        for (int kc = 0; kc < 2; kc++) {
            int k0 = kc * 8;
            uint32_t a[4][4];
            #pragma unroll
            for (int mt = 0; mt < 4; mt++) {
                int mb = wm*64 + mt*16;
                a[mt][0] = __float_as_uint(As[(mb + grp    )*GA_PAD + k0 + tg    ]);
                a[mt][1] = __float_as_uint(As[(mb + grp + 8)*GA_PAD + k0 + tg    ]);
                a[mt][2] = __float_as_uint(As[(mb + grp    )*GA_PAD + k0 + tg + 4]);
                a[mt][3] = __float_as_uint(As[(mb + grp + 8)*GA_PAD + k0 + tg + 4]);
            }
            #pragma unroll
            for (int nt = 0; nt < 8; nt++) {
                int nb = wn*64 + nt*8;
                uint32_t b0 = __float_as_uint(Bs[(k0 + tg    )*GB_PAD + nb + grp]);
                uint32_t b1 = __float_as_uint(Bs[(k0 + tg + 4)*GB_PAD + nb + grp]);
                #pragma unroll
                for (int mt = 0; mt < 4; mt++)
                    mma_tf32(d[mt][nt], a[mt], b0, b1);
            }
        }
        __syncthreads();
    }

    #pragma unroll
    for (int mt = 0; mt < 4; mt++) {
        #pragma unroll
        for (int nt = 0; nt < 8; nt++) {
            int r0 = m0 + wm*64 + mt*16 + grp;
            int col = n0 + wn*64 + nt*8 + 2*tg;
            if (r0 < N_)
                *(float2*)&dst[(size_t)r0*FO_ + col] = make_float2(d[mt][nt][0], d[mt][nt][1]);
            int r1 = r0 + 8;
            if (r1 < N_)
                *(float2*)&dst[(size_t)r1*FO_ + col] = make_float2(d[mt][nt][2], d[mt][nt][3]);
        }
    }
}

// ================== agg body: 1 warp per row (R12 config) ==================
__device__ void agg_body(float* __restrict__ out, int t, int blk) {
    int warp = threadIdx.x >> 5, lane = threadIdx.x & 31;
    int row = blk * 8 + warp;
    if (row >= N_) return;
    const float* dis = g_dis + (size_t)t*R_*N_;
    float disrow[R_];
    #pragma unroll
    for (int r = 0; r < R_; r++) disrow[r] = dis[r*N_ + row];
    float4 a0 = make_float4(0.f, 0.f, 0.f, 0.f);
    float4 a1 = make_float4(0.f, 0.f, 0.f, 0.f);
    int beg = g_off[t*(N_+1) + row], end = g_off[t*(N_+1) + row + 1];
    const uint32_t* ep = g_epack + (size_t)t*E_;
    for (int p = beg; p < end; p++) {
        uint32_t pk = ep[p];
        int r = pk & 3;
        int col = pk >> 2;
        float norm = disrow[r] * dis[r*N_ + col];
        if (norm != 0.f) {
            const float4* src = (const float4*)(g_Y + ((size_t)r*N_ + col) * FO_);
            float4 v0 = src[lane];
            float4 v1 = src[lane + 32];
            a0.x += v0.x*norm; a0.y += v0.y*norm; a0.z += v0.z*norm; a0.w += v0.w*norm;
            a1.x += v1.x*norm; a1.y += v1.y*norm; a1.z += v1.z*norm; a1.w += v1.w*norm;
        }
    }
    float4* dst = (float4*)(out + (size_t)t*N_*FO_ + (size_t)row*FO_);
    float4 o0 = dst[lane];
    float4 o1 = dst[lane + 32];
    o0.x = fmaxf(o0.x + a0.x, 0.f); o0.y = fmaxf(o0.y + a0.y, 0.f);
    o0.z = fmaxf(o0.z + a0.z, 0.f); o0.w = fmaxf(o0.w + a0.w, 0.f);
    o1.x = fmaxf(o1.x + a1.x, 0.f); o1.y = fmaxf(o1.y + a1.y, 0.f);
    o1.z = fmaxf(o1.z + a1.z, 0.f); o1.w = fmaxf(o1.w + a1.w, 0.f);
    dst[lane] = o0;
    dst[lane + 32] = o1;
}

// ================== merged per-t kernels (cells at LOW block indices) ==================
__global__ __launch_bounds__(128, 2) void k_gemm_cell1(
    float* __restrict__ out, int t,
    const float* sWz, const float* sUz, const float* sbz,
    const float* sWr, const float* sUr, const float* sbr,
    const float* rWz, const float* rUz, const float* rbz,
    const float* rWr, const float* rUr, const float* rbr,
    int parNext, int tNext, int doCell) {
    int z = blockIdx.z;
    if (z < 2*C_) {
        if (!doCell || blockIdx.x >= 16 || blockIdx.y != 0) return;
        cell1_sel(z & 1, z >> 1, sWz, sUz, sbz, sWr, sUr, sbr,
                  rWz, rUz, rbz, rWr, rUr, rbr, parNext, tNext, blockIdx.x);
    } else {
        gemm_body(out, t, z - 2*C_, blockIdx.x * 128, blockIdx.y * 128);
    }
}

__global__ __launch_bounds__(256) void k_agg_cell2(
    float* __restrict__ out, int t,
    const float* sWh, const float* sUh, const float* sbh,
    const float* rWh, const float* rUh, const float* rbh,
    int parNext, int tNext, int doCell) {
    int x = blockIdx.x;
    if (x < 80) {
        if (!doCell) return;
        int c = x >> 4, x16 = x & 15;
        const float* W = c ? rWh + (c-1)*MAT_ : sWh;
        const float* U = c ? rUh + (c-1)*MAT_ : sUh;
        const float* B = c ? rbh + (c-1)*MAT_ : sbh;
        cell2_body(W, U, B, g_zt + (size_t)(tNext*C_ + c)*MAT_,
                   g_Q[parNext] + c*MAT_, g_rst + c*MAT_, g_upd + c*MAT_,
                   g_Q[parNext ^ 1] + c*MAT_, g_Qc + c*MAT_, x16);
    } else {
        agg_body(out, t, x - 80);
    }
}

// ================== launcher ==================
extern "C" void kernel_launch(void* const* d_in, const int* in_sizes, int n_in,
                              void* d_out, int out_size) {
    const float* x       = (const float*)d_in[0];
    const float* mask    = (const float*)d_in[1];
    const float* Wself   = (const float*)d_in[2];
    const float* Wrel    = (const float*)d_in[3];
    const float* sWz     = (const float*)d_in[4];
    const float* sUz     = (const float*)d_in[5];
    const float* sbz     = (const float*)d_in[6];
    const float* sWr     = (const float*)d_in[7];
    const float* sUr     = (const float*)d_in[8];
    const float* sbr     = (const float*)d_in[9];
    const float* sWh     = (const float*)d_in[10];
    const float* sUh     = (const float*)d_in[11];
    const float* sbh     = (const float*)d_in[12];
    const float* s_sc    = (const float*)d_in[13];
    const float* rWz     = (const float*)d_in[14];
    const float* rUz     = (const float*)d_in[15];
    const float* rbz     = (const float*)d_in[16];
    const float* rWr     = (const float*)d_in[17];
    const float* rUr     = (const float*)d_in[18];
    const float* rbr     = (const float*)d_in[19];
    const float* rWh     = (const float*)d_in[20];
    const float* rUh     = (const float*)d_in[21];
    const float* rbh     = (const float*)d_in[22];
    const float* r_sc    = (const float*)d_in[23];
    const int*   ei      = (const int*)d_in[24];
    const int*   et      = (const int*)d_in[25];
    float* out = (float*)d_out;

    static bool attr_set = false;
    if (!attr_set) {
        cudaFuncSetAttribute(k_sel, cudaFuncAttributeMaxDynamicSharedMemorySize,
                             N_ * (int)sizeof(uint32_t));
        cudaFuncSetAttribute(k_gemm_cell1, cudaFuncAttributeMaxDynamicSharedMemorySize,
                             G_SMEM);
        attr_set = true;
    }

    // preamble: 3 launches (counters pre-zeroed by self-cleaning invariant)
    k_prep_all<<<PA_TOTAL, 256>>>(Wself, Wrel, x, mask, s_sc, r_sc, ei, et);
    k_sel<<<T_*C_ + T_ + SEL_DIS_BLOCKS, 1024, N_ * sizeof(uint32_t)>>>();
    k_zt_scatter<<<ZT_BLOCKS + T_*1250 + RZ_BLOCKS, 256>>>(x, ei, et);

    // t = 0 cells
    k_cell1_only<<<dim3(16, 1, 2*C_), 128>>>(sWz, sUz, sbz, sWr, sUr, sbr,
                                             rWz, rUz, rbz, rWr, rUr, rbr, 0, 0);
    k_cell2_only<<<dim3(16, 1, C_), 256>>>(sWh, sUh, sbh, rWh, rUh, rbh, 0, 0);

    // pipelined recurrence
    for (int t = 0; t < T_; t++) {
        int doCell = (t + 1 < T_) ? 1 : 0;
        int parN = (t + 1) & 1;
        k_gemm_cell1<<<dim3((N_ + 127)/128, 2, 2*C_ + C_), 128, G_SMEM>>>(
            out, t, sWz, sUz, sbz, sWr, sUr, sbr,
            rWz, rUz, rbz, rWr, rUr, rbr, parN, t + 1, doCell);
        k_agg_cell2<<<80 + 2500, 256>>>(
            out, t, sWh, sUh, sbh, rWh, rUh, rbh, parN, t + 1, doCell);
    }
}

// round 15
// speedup vs baseline: 1.0771x; 1.0449x over previous
#include <cuda_runtime.h>
#include <math.h>
#include <stdint.h>

#define T_ 3
#define N_ 20000
#define F_ 256
#define FO_ 256
#define E_ 320000
#define R_ 4
#define C_ 5
#define MAT_ (F_*FO_)

// ---------------- scratch ----------------
__device__ float g_scores[T_*C_*N_];
__device__ float g_vals  [T_*C_*FO_];
__device__ int   g_tidx  [T_*C_*FO_];
__device__ float g_zt    [T_*C_*MAT_];
__device__ float g_upd   [C_*MAT_];
__device__ float g_rst   [C_*MAT_];
__device__ float g_Q  [2][C_*MAT_];
__device__ float g_Qc    [C_*MAT_];
__device__ float g_xc    [T_*N_*F_];
__device__ float g_Y     [R_*N_*FO_];
__device__ int   g_degI  [T_*R_*N_];   // zero at entry (self-cleaned)
__device__ float g_dis   [T_*R_*N_];
__device__ int      g_cnt [T_*N_];     // zero at entry (self-cleaned)
__device__ int      g_off [T_*(N_+1)];
__device__ int      g_fill[T_*N_];
__device__ uint32_t g_epack[T_*E_];

extern __shared__ unsigned char s_dyn[];

__device__ __forceinline__ uint32_t f2key(float f) {
    uint32_t u = __float_as_uint(f);
    return (u & 0x80000000u) ? ~u : (u | 0x80000000u);
}
__device__ __forceinline__ float key2f(uint32_t k) {
    return (k & 0x80000000u) ? __uint_as_float(k & 0x7FFFFFFFu) : __uint_as_float(~k);
}
__device__ __forceinline__ float cvt_tf32(float f) {
    uint32_t r;
    asm("cvt.rna.tf32.f32 %0, %1;" : "=r"(r) : "f"(f));
    return __uint_as_float(r);
}
__device__ __forceinline__ float sigmoidf_(float v) { return 1.f / (1.f + expf(-v)); }

__device__ __forceinline__ void mma_tf32(float* d, const uint32_t* a, uint32_t b0, uint32_t b1) {
    asm volatile(
        "mma.sync.aligned.m16n8k8.row.col.f32.tf32.tf32.f32 "
        "{%0,%1,%2,%3}, {%4,%5,%6,%7}, {%8,%9}, {%0,%1,%2,%3};"
        : "+f"(d[0]), "+f"(d[1]), "+f"(d[2]), "+f"(d[3])
        : "r"(a[0]), "r"(a[1]), "r"(a[2]), "r"(a[3]), "r"(b0), "r"(b1));
}
__device__ __forceinline__ uint32_t smem_u32(const void* p) {
    uint32_t a;
    asm("{ .reg .u64 t; cvta.to.shared.u64 t, %1; cvt.u32.u64 %0, t; }" : "=r"(a) : "l"(p));
    return a;
}
__device__ __forceinline__ void cp_async16(uint32_t dst, const void* src) {
    asm volatile("cp.async.ca.shared.global [%0], [%1], 16;" :: "r"(dst), "l"(src) : "memory");
}
#define CP_COMMIT()  asm volatile("cp.async.commit_group;" ::: "memory")
#define CP_WAIT(n)   asm volatile("cp.async.wait_group %0;" :: "n"(n) : "memory")

// ================== L1: scores + edge count + initQ + xcvt ==================
#define PA_SCORE (T_*2500)
#define PA_CNT   (T_*1250)
#define PA_INIT  ((C_*MAT_)/256)
#define PA_XCVT  ((T_*N_*F_/4)/256)
#define PA_TOTAL (PA_SCORE + PA_CNT + PA_INIT + PA_XCVT)

__global__ __launch_bounds__(256) void k_prep_all(const float* __restrict__ Wself,
                                                  const float* __restrict__ Wrel,
                                                  const float* __restrict__ x,
                                                  const float* __restrict__ mask,
                                                  const float* __restrict__ s_sc,
                                                  const float* __restrict__ r_sc,
                                                  const int* __restrict__ ei,
                                                  const int* __restrict__ et) {
    int b = blockIdx.x, tid = threadIdx.x;
    if (b < PA_SCORE) {
        int t = b / 2500, blk = b - t*2500;
        __shared__ float sc[C_][F_];
        __shared__ float sden[C_];
        for (int i = tid; i < C_*F_; i += 256) {
            int c = i / F_, f = i - c*F_;
            sc[c][f] = (c == 0) ? s_sc[f] : r_sc[(c-1)*F_ + f];
        }
        __syncthreads();
        int warp = tid >> 5, lane = tid & 31;
        if (warp < C_) {
            float s = 0.f;
            #pragma unroll
            for (int q = 0; q < 8; q++) { float v = sc[warp][lane + q*32]; s += v*v; }
            for (int o = 16; o > 0; o >>= 1) s += __shfl_down_sync(0xffffffffu, s, o);
            if (lane == 0) sden[warp] = sqrtf(s) + 1e-8f;
        }
        __syncthreads();
        int n = blk * 8 + warp;
        if (n >= N_) return;
        const float4* xr = (const float4*)(x + ((size_t)t*N_ + n) * F_);
        float acc[C_] = {0.f, 0.f, 0.f, 0.f, 0.f};
        #pragma unroll
        for (int q = 0; q < 2; q++) {
            float4 xv = xr[lane + q*32];
            int e0 = (lane + q*32) * 4;
            #pragma unroll
            for (int c = 0; c < C_; c++) {
                acc[c] += xv.x * sc[c][e0]   + xv.y * sc[c][e0+1]
                        + xv.z * sc[c][e0+2] + xv.w * sc[c][e0+3];
            }
        }
        #pragma unroll
        for (int c = 0; c < C_; c++) {
            float v = acc[c];
            for (int o = 16; o > 0; o >>= 1) v += __shfl_down_sync(0xffffffffu, v, o);
            if (lane == 0)
                g_scores[(size_t)(t*C_ + c)*N_ + n] = v / sden[c] + mask[(size_t)t*N_ + n];
        }
    } else if (b < PA_SCORE + PA_CNT) {
        int idx = b - PA_SCORE;
        int t = idx / 1250;
        int e = (idx - t*1250)*256 + tid;
        if (e >= E_) return;
        int row = ei[(size_t)t*2*E_ + e];
        int r   = et[(size_t)t*E_ + e];
        atomicAdd(&g_degI[(t*R_ + r)*N_ + row], 1);
        atomicAdd(&g_cnt[t*N_ + row], 1);
    } else if (b < PA_SCORE + PA_CNT + PA_INIT) {
        int i = (b - PA_SCORE - PA_CNT)*256 + tid;
        int c = i / MAT_, off = i - c*MAT_;
        g_Q[0][i] = (c == 0) ? Wself[off] : Wrel[(c-1)*MAT_ + off];
    } else {
        int i = (b - PA_SCORE - PA_CNT - PA_INIT)*256 + tid;
        float4 v = ((const float4*)x)[i];
        v.x = cvt_tf32(v.x); v.y = cvt_tf32(v.y);
        v.z = cvt_tf32(v.z); v.w = cvt_tf32(v.w);
        ((float4*)g_xc)[i] = v;
    }
}

// ================== L2: topk + scan + dis ==================
__device__ void topk_body(int tc) {
    uint32_t* s_keys = (uint32_t*)s_dyn;
    __shared__ int      hist[256];
    __shared__ int      sfx[256];
    __shared__ uint32_t selKey[256];
    __shared__ int      selIdx[256];
    __shared__ uint32_t s_prefix;
    __shared__ int      s_remaining, s_eqCount, s_idxTh, s_cnt;

    int tid = threadIdx.x;
    const float* sc = g_scores + (size_t)tc * N_;

    if (tid < 256) hist[tid] = 0;
    if (tid == 0) { s_prefix = 0u; s_remaining = FO_; s_idxTh = 0x7FFFFFFF; s_eqCount = FO_; }
    __syncthreads();

    for (int i = tid; i < N_; i += 1024) {
        uint32_t k = f2key(sc[i]);
        s_keys[i] = k;
        atomicAdd(&hist[k >> 24], 1);
    }
    __syncthreads();

    #pragma unroll
    for (int pass = 3; pass >= 0; pass--) {
        int shift = pass * 8;
        if (pass < 3) {
            if (tid < 256) hist[tid] = 0;
            __syncthreads();
            uint32_t prefix = s_prefix;
            uint32_t pmask = 0xFFFFFFFFu << (shift + 8);
            for (int i = tid; i < N_; i += 1024) {
                uint32_t k = s_keys[i];
                if ((k & pmask) == (prefix & pmask))
                    atomicAdd(&hist[(k >> shift) & 0xFF], 1);
            }
            __syncthreads();
        }
        if (tid < 256) sfx[tid] = hist[tid];
        __syncthreads();
        #pragma unroll
        for (int o = 1; o < 256; o <<= 1) {
            int v = 0;
            if (tid < 256) v = sfx[tid] + ((tid + o < 256) ? sfx[tid + o] : 0);
            __syncthreads();
            if (tid < 256) sfx[tid] = v;
            __syncthreads();
        }
        int rem = s_remaining;
        __syncthreads();
        if (tid < 256) {
            int s  = sfx[tid];
            int sn = (tid < 255) ? sfx[tid + 1] : 0;
            if (s >= rem && sn < rem) {
                s_prefix |= ((uint32_t)tid) << shift;
                s_remaining = rem - sn;
                if (pass == 0) s_eqCount = hist[tid];
            }
        }
        __syncthreads();
    }
    uint32_t kth = s_prefix;
    int need = s_remaining;

    if (need < s_eqCount) {
        if (tid == 0) { s_prefix = 0u; s_remaining = need; }
        __syncthreads();
        #pragma unroll
        for (int pass = 1; pass >= 0; pass--) {
            int shift = pass * 8;
            if (tid < 256) hist[tid] = 0;
            __syncthreads();
            uint32_t prefixI = s_prefix;
            for (int i = tid; i < N_; i += 1024) {
                if (s_keys[i] == kth) {
                    if (pass == 1 || (((uint32_t)i >> 8) & 0xFF) == ((prefixI >> 8) & 0xFF))
                        atomicAdd(&hist[((uint32_t)i >> shift) & 0xFF], 1);
                }
            }
            __syncthreads();
            if (tid == 0) {
                int rem = s_remaining;
                uint32_t pfx = s_prefix;
                for (int bb = 0; bb < 256; bb++) {
                    int cnt = hist[bb];
                    if (cnt >= rem) { pfx |= ((uint32_t)bb) << shift; break; }
                    rem -= cnt;
                }
                s_remaining = rem;
                s_prefix = pfx;
            }
            __syncthreads();
        }
        if (tid == 0) s_idxTh = (int)s_prefix;
    }
    if (tid == 0) s_cnt = 0;
    __syncthreads();
    int idxTh = s_idxTh;

    for (int i = tid; i < N_; i += 1024) {
        uint32_t k = s_keys[i];
        if (k > kth || (k == kth && i <= idxTh)) {
            int p = atomicAdd(&s_cnt, 1);
            selKey[p] = k;
            selIdx[p] = i;
        }
    }
    __syncthreads();

    for (int k = 2; k <= 256; k <<= 1) {
        for (int j = k >> 1; j > 0; j >>= 1) {
            if (tid < 256) {
                int ixj = tid ^ j;
                if (ixj > tid) {
                    bool desc = ((tid & k) == 0);
                    uint32_t ka = selKey[tid], kb = selKey[ixj];
                    int ia = selIdx[tid], ib = selIdx[ixj];
                    bool aGreater = (ka > kb) || (ka == kb && ia < ib);
                    bool doswap = desc ? !aGreater : aGreater;
                    if (doswap) {
                        selKey[tid] = kb; selKey[ixj] = ka;
                        selIdx[tid] = ib; selIdx[ixj] = ia;
                    }
                }
            }
            __syncthreads();
        }
    }

    if (tid < 256) {
        g_vals[(size_t)tc*FO_ + tid] = key2f(selKey[tid]);
        g_tidx[(size_t)tc*FO_ + tid] = selIdx[tid];
    }
}

__device__ void scan_body(int t) {
    __shared__ int part[1024];
    const int* cnt = g_cnt + t*N_;
    int* off = g_off + t*(N_+1);
    int* fill = g_fill + t*N_;
    int tid = threadIdx.x;
    const int CH = (N_ + 1023) / 1024;
    int base = tid * CH;
    int s = 0;
    for (int i = 0; i < CH; i++) {
        int idx = base + i;
        if (idx < N_) s += cnt[idx];
    }
    part[tid] = s;
    __syncthreads();
    for (int o = 1; o < 1024; o <<= 1) {
        int v = (tid >= o) ? part[tid - o] : 0;
        __syncthreads();
        part[tid] += v;
        __syncthreads();
    }
    int run = (tid == 0) ? 0 : part[tid - 1];
    for (int i = 0; i < CH; i++) {
        int idx = base + i;
        if (idx < N_) {
            off[idx] = run;
            run += cnt[idx];
            fill[idx] = 0;
        }
    }
    if (tid == 0) off[N_] = E_;
}

#define SEL_DIS_BLOCKS (((T_*R_*N_)+1023)/1024)
__global__ __launch_bounds__(1024) void k_sel() {
    int b = blockIdx.x;
    if (b < T_*C_) {
        topk_body(b);
    } else if (b < T_*C_ + T_) {
        scan_body(b - T_*C_);
    } else {
        int i = (b - T_*C_ - T_)*1024 + threadIdx.x;
        if (i < T_*R_*N_) {
            int d = g_degI[i];
            g_dis[i] = (d > 0) ? (1.f / sqrtf((float)d)) : 0.f;
        }
    }
}

// ================== L3: zt + scatter + re-zero ==================
#define ZT_BLOCKS ((T_*C_*FO_)/4)
#define RZ_BLOCKS (((T_*R_*N_)+255)/256)
__global__ __launch_bounds__(256) void k_zt_scatter(const float* __restrict__ x,
                                                    const int* __restrict__ ei,
                                                    const int* __restrict__ et) {
    int b = blockIdx.x, tid = threadIdx.x;
    if (b < ZT_BLOCKS) {
        int sub = tid >> 6, l = tid & 63;
        int jct = b*4 + sub;
        int j = jct & 255;
        int cc = jct >> 8;
        int c = cc % C_, t = cc / C_;
        int tc = t*C_ + c;
        int idx = g_tidx[(size_t)tc*FO_ + j];
        float tv = tanhf(g_vals[(size_t)tc*FO_ + j]);
        const float4* xr = (const float4*)(x + ((size_t)t*N_ + idx) * F_);
        float4 v = xr[l];
        v.x *= tv; v.y *= tv; v.z *= tv; v.w *= tv;
        ((float4*)(g_zt + ((size_t)tc*FO_ + j) * F_))[l] = v;
    } else if (b < ZT_BLOCKS + T_*1250) {
        int idx = b - ZT_BLOCKS;
        int t = idx / 1250;
        int e = (idx - t*1250)*256 + tid;
        if (e >= E_) return;
        int row = ei[(size_t)t*2*E_ + e];
        int col = ei[(size_t)t*2*E_ + E_ + e];
        int r   = et[(size_t)t*E_ + e];
        int pos = g_off[t*(N_+1) + row] + atomicAdd(&g_fill[t*N_ + row], 1);
        g_epack[(size_t)t*E_ + pos] = ((uint32_t)col << 2) | (uint32_t)r;
    } else {
        int i = (b - ZT_BLOCKS - T_*1250)*256 + tid;
        if (i < T_*R_*N_) g_degI[i] = 0;
        if (i < T_*N_) g_cnt[i] = 0;
    }
}

// ================== cell bodies: cp.async double-buffered, cvt at fragment read ==================
// smem layouts: m/n-major tiles [64][20] (conflict-free), k-major tiles [16][72] (conflict-free)

__device__ void cell1_body(const float* W, const float* U, const float* B,
                           const float* Z, const float* Qm, float* OUT, int x16) {
    __shared__ float sm1[2][2560];   // per stage: A [64*20]=1280 @0, B 1280 @1280
    int tid = threadIdx.x, lane = tid & 31, wid = tid >> 5;
    int wm = wid >> 1, wn = wid & 1;
    int grp = lane >> 2, tg = lane & 3;
    int i0 = (x16 >> 2) * 64, j0 = (x16 & 3) * 64;
    uint32_t smb[2] = { smem_u32(&sm1[0][0]), smem_u32(&sm1[1][0]) };

    float d[2][4][4];
    #pragma unroll
    for (int mt = 0; mt < 2; mt++)
        #pragma unroll
        for (int nt = 0; nt < 4; nt++)
            #pragma unroll
            for (int q = 0; q < 4; q++) d[mt][nt][q] = 0.f;

    // ---- phase 0: A = W rows [64x16], B = Z rows [64x16] (both m/n-major) ----
    auto load0 = [&](int stg, int kb) {
        uint32_t sa = smb[stg];
        #pragma unroll
        for (int i = 0; i < 2; i++) {
            int idx = tid + i*128;
            int row = idx >> 2, ch = (idx & 3) * 4;
            cp_async16(sa + (uint32_t)(row*20 + ch)*4, W + (size_t)(i0+row)*256 + kb + ch);
            cp_async16(sa + (uint32_t)(1280 + row*20 + ch)*4, Z + (size_t)(j0+row)*256 + kb + ch);
        }
        CP_COMMIT();
    };
    load0(0, 0);
    #pragma unroll 1
    for (int s = 0; s < 16; s++) {
        if (s + 1 < 16) load0((s + 1) & 1, (s + 1) * 16);
        if (s + 1 < 16) { CP_WAIT(1); } else { CP_WAIT(0); }
        __syncthreads();
        const float* As = sm1[s & 1];
        const float* Bs = As + 1280;
        #pragma unroll
        for (int kc = 0; kc < 2; kc++) {
            int k0 = kc * 8;
            uint32_t afr[2][4];
            #pragma unroll
            for (int mt = 0; mt < 2; mt++) {
                int mb = wm*32 + mt*16;
                afr[mt][0] = __float_as_uint(cvt_tf32(As[(mb+grp  )*20 + k0+tg  ]));
                afr[mt][1] = __float_as_uint(cvt_tf32(As[(mb+grp+8)*20 + k0+tg  ]));
                afr[mt][2] = __float_as_uint(cvt_tf32(As[(mb+grp  )*20 + k0+tg+4]));
                afr[mt][3] = __float_as_uint(cvt_tf32(As[(mb+grp+8)*20 + k0+tg+4]));
            }
            #pragma unroll
            for (int nt = 0; nt < 4; nt++) {
                int nb = wn*32 + nt*8;
                uint32_t b0 = __float_as_uint(cvt_tf32(Bs[(nb+grp)*20 + k0+tg  ]));
                uint32_t b1 = __float_as_uint(cvt_tf32(Bs[(nb+grp)*20 + k0+tg+4]));
                #pragma unroll
                for (int mt = 0; mt < 2; mt++) mma_tf32(d[mt][nt], afr[mt], b0, b1);
            }
        }
        __syncthreads();
    }

    // ---- phase 1: A = U rows [64x16], B = Q [16 krows x 64n] (k-major) ----
    auto load1 = [&](int stg, int kb) {
        uint32_t sa = smb[stg];
        #pragma unroll
        for (int i = 0; i < 2; i++) {
            int idx = tid + i*128;
            int row = idx >> 2, ch = (idx & 3) * 4;
            cp_async16(sa + (uint32_t)(row*20 + ch)*4, U + (size_t)(i0+row)*256 + kb + ch);
            int kr = idx >> 4, nc = (idx & 15) * 4;
            cp_async16(sa + (uint32_t)(1280 + kr*72 + nc)*4, Qm + (size_t)(kb+kr)*256 + j0 + nc);
        }
        CP_COMMIT();
    };
    load1(0, 0);
    #pragma unroll 1
    for (int s = 0; s < 16; s++) {
        if (s + 1 < 16) load1((s + 1) & 1, (s + 1) * 16);
        if (s + 1 < 16) { CP_WAIT(1); } else { CP_WAIT(0); }
        __syncthreads();
        const float* As = sm1[s & 1];
        const float* Bs = As + 1280;
        #pragma unroll
        for (int kc = 0; kc < 2; kc++) {
            int k0 = kc * 8;
            uint32_t afr[2][4];
            #pragma unroll
            for (int mt = 0; mt < 2; mt++) {
                int mb = wm*32 + mt*16;
                afr[mt][0] = __float_as_uint(cvt_tf32(As[(mb+grp  )*20 + k0+tg  ]));
                afr[mt][1] = __float_as_uint(cvt_tf32(As[(mb+grp+8)*20 + k0+tg  ]));
                afr[mt][2] = __float_as_uint(cvt_tf32(As[(mb+grp  )*20 + k0+tg+4]));
                afr[mt][3] = __float_as_uint(cvt_tf32(As[(mb+grp+8)*20 + k0+tg+4]));
            }
            #pragma unroll
            for (int nt = 0; nt < 4; nt++) {
                int nb = wn*32 + nt*8;
                uint32_t b0 = __float_as_uint(cvt_tf32(Bs[(k0+tg  )*72 + nb+grp]));
                uint32_t b1 = __float_as_uint(cvt_tf32(Bs[(k0+tg+4)*72 + nb+grp]));
                #pragma unroll
                for (int mt = 0; mt < 2; mt++) mma_tf32(d[mt][nt], afr[mt], b0, b1);
            }
        }
        __syncthreads();
    }

    #pragma unroll
    for (int mt = 0; mt < 2; mt++) {
        #pragma unroll
        for (int nt = 0; nt < 4; nt++) {
            int r0 = i0 + wm*32 + mt*16 + grp;
            int col = j0 + wn*32 + nt*8 + 2*tg;
            float2 bi0 = *(const float2*)(B + (size_t)r0*256 + col);
            *(float2*)&OUT[(size_t)r0*256 + col] =
                make_float2(sigmoidf_(d[mt][nt][0] + bi0.x), sigmoidf_(d[mt][nt][1] + bi0.y));
            int r1 = r0 + 8;
            float2 bi1 = *(const float2*)(B + (size_t)r1*256 + col);
            *(float2*)&OUT[(size_t)r1*256 + col] =
                make_float2(sigmoidf_(d[mt][nt][2] + bi1.x), sigmoidf_(d[mt][nt][3] + bi1.y));
        }
    }
}

__device__ void cell2_body(const float* W, const float* U, const float* B,
                           const float* Z, const float* Qin, const float* RST,
                           const float* UPD, float* Qout, float* Qc, int x16) {
    __shared__ float sm2[2][3584];   // A 1280 @0, B 1280 @1280, R 1152 @2432 (phase1)
    int tid = threadIdx.x, lane = tid & 31, wid = tid >> 5;
    int wm = wid >> 2, wn = wid & 3;
    int grp = lane >> 2, tg = lane & 3;
    int i0 = (x16 >> 2) * 64, j0 = (x16 & 3) * 64;
    uint32_t smb[2] = { smem_u32(&sm2[0][0]), smem_u32(&sm2[1][0]) };

    float d[2][2][4];
    #pragma unroll
    for (int mt = 0; mt < 2; mt++)
        #pragma unroll
        for (int nt = 0; nt < 2; nt++)
            #pragma unroll
            for (int q = 0; q < 4; q++) d[mt][nt][q] = 0.f;

    // ---- phase 0: A = W rows, B = Z rows ----
    auto load0 = [&](int stg, int kb) {
        uint32_t sa = smb[stg];
        int idx = tid;   // 256 threads, 1 chunk per array each
        int row = idx >> 2, ch = (idx & 3) * 4;
        cp_async16(sa + (uint32_t)(row*20 + ch)*4, W + (size_t)(i0+row)*256 + kb + ch);
        cp_async16(sa + (uint32_t)(1280 + row*20 + ch)*4, Z + (size_t)(j0+row)*256 + kb + ch);
        CP_COMMIT();
    };
    load0(0, 0);
    #pragma unroll 1
    for (int s = 0; s < 16; s++) {
        if (s + 1 < 16) load0((s + 1) & 1, (s + 1) * 16);
        if (s + 1 < 16) { CP_WAIT(1); } else { CP_WAIT(0); }
        __syncthreads();
        const float* As = sm2[s & 1];
        const float* Bs = As + 1280;
        #pragma unroll
        for (int kc = 0; kc < 2; kc++) {
            int k0 = kc * 8;
            uint32_t afr[2][4];
            #pragma unroll
            for (int mt = 0; mt < 2; mt++) {
                int mb = wm*32 + mt*16;
                afr[mt][0] = __float_as_uint(cvt_tf32(As[(mb+grp  )*20 + k0+tg  ]));
                afr[mt][1] = __float_as_uint(cvt_tf32(As[(mb+grp+8)*20 + k0+tg  ]));
                afr[mt][2] = __float_as_uint(cvt_tf32(As[(mb+grp  )*20 + k0+tg+4]));
                afr[mt][3] = __float_as_uint(cvt_tf32(As[(mb+grp+8)*20 + k0+tg+4]));
            }
            #pragma unroll
            for (int nt = 0; nt < 2; nt++) {
                int nb = wn*16 + nt*8;
                uint32_t b0 = __float_as_uint(cvt_tf32(Bs[(nb+grp)*20 + k0+tg  ]));
                uint32_t b1 = __float_as_uint(cvt_tf32(Bs[(nb+grp)*20 + k0+tg+4]));
                #pragma unroll
                for (int mt = 0; mt < 2; mt++) mma_tf32(d[mt][nt], afr[mt], b0, b1);
            }
        }
        __syncthreads();
    }

    // ---- phase 1: A = U rows; B = Qin [16x64 k-major]; R = RST [16x64 k-major] ----
    auto load1 = [&](int stg, int kb) {
        uint32_t sa = smb[stg];
        int idx = tid;
        int row = idx >> 2, ch = (idx & 3) * 4;
        cp_async16(sa + (uint32_t)(row*20 + ch)*4, U + (size_t)(i0+row)*256 + kb + ch);
        int kr = idx >> 4, nc = (idx & 15) * 4;
        cp_async16(sa + (uint32_t)(1280 + kr*72 + nc)*4, Qin + (size_t)(kb+kr)*256 + j0 + nc);
        cp_async16(sa + (uint32_t)(2432 + kr*72 + nc)*4, RST + (size_t)(kb+kr)*256 + j0 + nc);
        CP_COMMIT();
    };
    load1(0, 0);
    #pragma unroll 1
    for (int s = 0; s < 16; s++) {
        if (s + 1 < 16) load1((s + 1) & 1, (s + 1) * 16);
        if (s + 1 < 16) { CP_WAIT(1); } else { CP_WAIT(0); }
        __syncthreads();
        const float* As = sm2[s & 1];
        const float* Bq = As + 1280;
        const float* Br = As + 2432;
        #pragma unroll
        for (int kc = 0; kc < 2; kc++) {
            int k0 = kc * 8;
            uint32_t afr[2][4];
            #pragma unroll
            for (int mt = 0; mt < 2; mt++) {
                int mb = wm*32 + mt*16;
                afr[mt][0] = __float_as_uint(cvt_tf32(As[(mb+grp  )*20 + k0+tg  ]));
                afr[mt][1] = __float_as_uint(cvt_tf32(As[(mb+grp+8)*20 + k0+tg  ]));
                afr[mt][2] = __float_as_uint(cvt_tf32(As[(mb+grp  )*20 + k0+tg+4]));
                afr[mt][3] = __float_as_uint(cvt_tf32(As[(mb+grp+8)*20 + k0+tg+4]));
            }
            #pragma unroll
            for (int nt = 0; nt < 2; nt++) {
                int nb = wn*16 + nt*8;
                uint32_t b0 = __float_as_uint(cvt_tf32(Bq[(k0+tg  )*72 + nb+grp] * Br[(k0+tg  )*72 + nb+grp]));
                uint32_t b1 = __float_as_uint(cvt_tf32(Bq[(k0+tg+4)*72 + nb+grp] * Br[(k0+tg+4)*72 + nb+grp]));
                #pragma unroll
                for (int mt = 0; mt < 2; mt++) mma_tf32(d[mt][nt], afr[mt], b0, b1);
            }
        }
        __syncthreads();
    }

    #pragma unroll
    for (int mt = 0; mt < 2; mt++) {
        #pragma unroll
        for (int nt = 0; nt < 2; nt++) {
            #pragma unroll
            for (int half = 0; half < 2; half++) {
                int r = i0 + wm*32 + mt*16 + grp + half*8;
                int col = j0 + wn*16 + nt*8 + 2*tg;
                float d0 = d[mt][nt][half*2], d1 = d[mt][nt][half*2 + 1];
                float2 bi = *(const float2*)(B + (size_t)r*256 + col);
                float2 up = *(const float2*)(UPD + (size_t)r*256 + col);
                float2 qi = *(const float2*)(Qin + (size_t)r*256 + col);
                float h0 = tanhf(d0 + bi.x), h1 = tanhf(d1 + bi.y);
                float v0 = (1.f - up.x)*qi.x + up.x*h0;
                float v1 = (1.f - up.y)*qi.y + up.y*h1;
                *(float2*)&Qout[(size_t)r*256 + col] = make_float2(v0, v1);
                *(float2*)&Qc[(size_t)r*256 + col] = make_float2(cvt_tf32(v0), cvt_tf32(v1));
            }
        }
    }
}

__device__ __forceinline__ void cell1_sel(
    int o, int c,
    const float* sWz, const float* sUz, const float* sbz,
    const float* sWr, const float* sUr, const float* sbr,
    const float* rWz, const float* rUz, const float* rbz,
    const float* rWr, const float* rUr, const float* rbr,
    int par, int t, int x16) {
    const float *W, *U, *B;
    if (o == 0) { W = c ? rWz + (c-1)*MAT_ : sWz; U = c ? rUz + (c-1)*MAT_ : sUz; B = c ? rbz + (c-1)*MAT_ : sbz; }
    else        { W = c ? rWr + (c-1)*MAT_ : sWr; U = c ? rUr + (c-1)*MAT_ : sUr; B = c ? rbr + (c-1)*MAT_ : sbr; }
    cell1_body(W, U, B, g_zt + (size_t)(t*C_ + c)*MAT_, g_Q[par] + c*MAT_,
               (o == 0 ? g_upd : g_rst) + c*MAT_, x16);
}

__global__ __launch_bounds__(128) void k_cell1_only(
    const float* sWz, const float* sUz, const float* sbz,
    const float* sWr, const float* sUr, const float* sbr,
    const float* rWz, const float* rUz, const float* rbz,
    const float* rWr, const float* rUr, const float* rbr,
    int par, int t) {
    int u = blockIdx.z;
    cell1_sel(u & 1, u >> 1, sWz, sUz, sbz, sWr, sUr, sbr,
              rWz, rUz, rbz, rWr, rUr, rbr, par, t, blockIdx.x);
}
__global__ __launch_bounds__(256) void k_cell2_only(
    const float* sWh, const float* sUh, const float* sbh,
    const float* rWh, const float* rUh, const float* rbh,
    int par, int t) {
    int c = blockIdx.z;
    const float* W = c ? rWh + (c-1)*MAT_ : sWh;
    const float* U = c ? rUh + (c-1)*MAT_ : sUh;
    const float* B = c ? rbh + (c-1)*MAT_ : sbh;
    cell2_body(W, U, B, g_zt + (size_t)(t*C_ + c)*MAT_,
               g_Q[par] + c*MAT_, g_rst + c*MAT_, g_upd + c*MAT_,
               g_Q[par ^ 1] + c*MAT_, g_Qc + c*MAT_, blockIdx.x);
}

// ================== big GEMM: 128x128 tile, 128 threads, 3-stage cp.async ==================
#define GA_PAD 20
#define GB_PAD 136
#define G_STAGE (128*GA_PAD*4 + 16*GB_PAD*4)
#define G_NSTG  3
#define G_SMEM  (G_NSTG*G_STAGE)

__device__ void gemm_body(float* __restrict__ out, int t, int c, int m0, int n0) {
    const float* Ag = g_xc + (size_t)t*N_*F_;
    const float* Bg = g_Qc + (size_t)c*MAT_;
    float* dst = (c == 0) ? out + (size_t)t*N_*FO_ : g_Y + (size_t)(c-1)*N_*FO_;

    float* smf = (float*)s_dyn;
    uint32_t smb = smem_u32(s_dyn);
    int tid = threadIdx.x, wid = tid >> 5, lane = tid & 31;
    int wm = wid >> 1, wn = wid & 1;
    int grp = lane >> 2, tg = lane & 3;

    float d[4][8][4];
    #pragma unroll
    for (int mt = 0; mt < 4; mt++)
        #pragma unroll
        for (int nt = 0; nt < 8; nt++)
            #pragma unroll
            for (int q = 0; q < 4; q++) d[mt][nt][q] = 0.f;

    auto load_stage = [&](int stg, int kb) {
        uint32_t sa = smb + stg*G_STAGE;
        uint32_t sb = sa + 128*GA_PAD*4;
        #pragma unroll
        for (int i = 0; i < 4; i++) {
            int idx = tid + i*128;
            int row = idx >> 2, ch = idx & 3;
            int gr = m0 + row;
            uint32_t dsta = sa + (uint32_t)(row*GA_PAD + ch*4)*4;
            if (gr < N_) {
                cp_async16(dsta, Ag + (size_t)gr*F_ + kb + ch*4);
            } else {
                *(float4*)(s_dyn + (dsta - smb)) = make_float4(0.f, 0.f, 0.f, 0.f);
            }
        }
        #pragma unroll
        for (int i = 0; i < 4; i++) {
            int idx = tid + i*128;
            int kr = idx >> 5, nch = idx & 31;
            uint32_t dstb = sb + (uint32_t)(kr*GB_PAD + nch*4)*4;
            cp_async16(dstb, Bg + (size_t)(kb + kr)*FO_ + n0 + nch*4);
        }
        CP_COMMIT();
    };

    load_stage(0, 0);
    load_stage(1, 16);

    #pragma unroll 1
    for (int step = 0; step < 16; step++) {
        if (step + 2 < 16) load_stage((step + 2) % G_NSTG, (step + 2) * 16);
        if (step + 2 < 16)      { CP_WAIT(2); }
        else if (step + 1 < 16) { CP_WAIT(1); }
        else                    { CP_WAIT(0); }
        __syncthreads();

        const float* As = smf + (step % G_NSTG) * (G_STAGE/4);
        const float* Bs = As + 128*GA_PAD;

        #pragma unroll
        for (int kc = 0; kc < 2; kc++) {
            int k0 = kc * 8;
            uint32_t a[4][4];
            #pragma unroll
            for (int mt = 0; mt < 4; mt++) {
                int mb = wm*64 + mt*16;
                a[mt][0] = __float_as_uint(As[(mb + grp    )*GA_PAD + k0 + tg    ]);
                a[mt][1] = __float_as_uint(As[(mb + grp + 8)*GA_PAD + k0 + tg    ]);
                a[mt][2] = __float_as_uint(As[(mb + grp    )*GA_PAD + k0 + tg + 4]);
                a[mt][3] = __float_as_uint(As[(mb + grp + 8)*GA_PAD + k0 + tg + 4]);
            }
            #pragma unroll
            for (int nt = 0; nt < 8; nt++) {
                int nb = wn*64 + nt*8;
                uint32_t b0 = __float_as_uint(Bs[(k0 + tg    )*GB_PAD + nb + grp]);
                uint32_t b1 = __float_as_uint(Bs[(k0 + tg + 4)*GB_PAD + nb + grp]);
                #pragma unroll
                for (int mt = 0; mt < 4; mt++)
                    mma_tf32(d[mt][nt], a[mt], b0, b1);
            }
        }
        __syncthreads();
    }

    #pragma unroll
    for (int mt = 0; mt < 4; mt++) {
        #pragma unroll
        for (int nt = 0; nt < 8; nt++) {
            int r0 = m0 + wm*64 + mt*16 + grp;
            int col = n0 + wn*64 + nt*8 + 2*tg;
            if (r0 < N_)
                *(float2*)&dst[(size_t)r0*FO_ + col] = make_float2(d[mt][nt][0], d[mt][nt][1]);
            int r1 = r0 + 8;
            if (r1 < N_)
                *(float2*)&dst[(size_t)r1*FO_ + col] = make_float2(d[mt][nt][2], d[mt][nt][3]);
        }
    }
}

// ================== agg body: 1 warp per row ==================
__device__ void agg_body(float* __restrict__ out, int t, int blk) {
    int warp = threadIdx.x >> 5, lane = threadIdx.x & 31;
    int row = blk * 8 + warp;
    if (row >= N_) return;
    const float* dis = g_dis + (size_t)t*R_*N_;
    float disrow[R_];
    #pragma unroll
    for (int r = 0; r < R_; r++) disrow[r] = dis[r*N_ + row];
    float4 a0 = make_float4(0.f, 0.f, 0.f, 0.f);
    float4 a1 = make_float4(0.f, 0.f, 0.f, 0.f);
    int beg = g_off[t*(N_+1) + row], end = g_off[t*(N_+1) + row + 1];
    const uint32_t* ep = g_epack + (size_t)t*E_;
    for (int p = beg; p < end; p++) {
        uint32_t pk = ep[p];
        int r = pk & 3;
        int col = pk >> 2;
        float norm = disrow[r] * dis[r*N_ + col];
        if (norm != 0.f) {
            const float4* src = (const float4*)(g_Y + ((size_t)r*N_ + col) * FO_);
            float4 v0 = src[lane];
            float4 v1 = src[lane + 32];
            a0.x += v0.x*norm; a0.y += v0.y*norm; a0.z += v0.z*norm; a0.w += v0.w*norm;
            a1.x += v1.x*norm; a1.y += v1.y*norm; a1.z += v1.z*norm; a1.w += v1.w*norm;
        }
    }
    float4* dst = (float4*)(out + (size_t)t*N_*FO_ + (size_t)row*FO_);
    float4 o0 = dst[lane];
    float4 o1 = dst[lane + 32];
    o0.x = fmaxf(o0.x + a0.x, 0.f); o0.y = fmaxf(o0.y + a0.y, 0.f);
    o0.z = fmaxf(o0.z + a0.z, 0.f); o0.w = fmaxf(o0.w + a0.w, 0.f);
    o1.x = fmaxf(o1.x + a1.x, 0.f); o1.y = fmaxf(o1.y + a1.y, 0.f);
    o1.z = fmaxf(o1.z + a1.z, 0.f); o1.w = fmaxf(o1.w + a1.w, 0.f);
    dst[lane] = o0;
    dst[lane + 32] = o1;
}

// ================== merged per-t kernels (cells at LOW block indices) ==================
__global__ __launch_bounds__(128, 2) void k_gemm_cell1(
    float* __restrict__ out, int t,
    const float* sWz, const float* sUz, const float* sbz,
    const float* sWr, const float* sUr, const float* sbr,
    const float* rWz, const float* rUz, const float* rbz,
    const float* rWr, const float* rUr, const float* rbr,
    int parNext, int tNext, int doCell) {
    int z = blockIdx.z;
    if (z < 2*C_) {
        if (!doCell || blockIdx.x >= 16 || blockIdx.y != 0) return;
        cell1_sel(z & 1, z >> 1, sWz, sUz, sbz, sWr, sUr, sbr,
                  rWz, rUz, rbz, rWr, rUr, rbr, parNext, tNext, blockIdx.x);
    } else {
        gemm_body(out, t, z - 2*C_, blockIdx.x * 128, blockIdx.y * 128);
    }
}

__global__ __launch_bounds__(256) void k_agg_cell2(
    float* __restrict__ out, int t,
    const float* sWh, const float* sUh, const float* sbh,
    const float* rWh, const float* rUh, const float* rbh,
    int parNext, int tNext, int doCell) {
    int x = blockIdx.x;
    if (x < 80) {
        if (!doCell) return;
        int c = x >> 4, x16 = x & 15;
        const float* W = c ? rWh + (c-1)*MAT_ : sWh;
        const float* U = c ? rUh + (c-1)*MAT_ : sUh;
        const float* B = c ? rbh + (c-1)*MAT_ : sbh;
        cell2_body(W, U, B, g_zt + (size_t)(tNext*C_ + c)*MAT_,
                   g_Q[parNext] + c*MAT_, g_rst + c*MAT_, g_upd + c*MAT_,
                   g_Q[parNext ^ 1] + c*MAT_, g_Qc + c*MAT_, x16);
    } else {
        agg_body(out, t, x - 80);
    }
}

// ================== launcher ==================
extern "C" void kernel_launch(void* const* d_in, const int* in_sizes, int n_in,
                              void* d_out, int out_size) {
    const float* x       = (const float*)d_in[0];
    const float* mask    = (const float*)d_in[1];
    const float* Wself   = (const float*)d_in[2];
    const float* Wrel    = (const float*)d_in[3];
    const float* sWz     = (const float*)d_in[4];
    const float* sUz     = (const float*)d_in[5];
    const float* sbz     = (const float*)d_in[6];
    const float* sWr     = (const float*)d_in[7];
    const float* sUr     = (const float*)d_in[8];
    const float* sbr     = (const float*)d_in[9];
    const float* sWh     = (const float*)d_in[10];
    const float* sUh     = (const float*)d_in[11];
    const float* sbh     = (const float*)d_in[12];
    const float* s_sc    = (const float*)d_in[13];
    const float* rWz     = (const float*)d_in[14];
    const float* rUz     = (const float*)d_in[15];
    const float* rbz     = (const float*)d_in[16];
    const float* rWr     = (const float*)d_in[17];
    const float* rUr     = (const float*)d_in[18];
    const float* rbr     = (const float*)d_in[19];
    const float* rWh     = (const float*)d_in[20];
    const float* rUh     = (const float*)d_in[21];
    const float* rbh     = (const float*)d_in[22];
    const float* r_sc    = (const float*)d_in[23];
    const int*   ei      = (const int*)d_in[24];
    const int*   et      = (const int*)d_in[25];
    float* out = (float*)d_out;

    static bool attr_set = false;
    if (!attr_set) {
        cudaFuncSetAttribute(k_sel, cudaFuncAttributeMaxDynamicSharedMemorySize,
                             N_ * (int)sizeof(uint32_t));
        cudaFuncSetAttribute(k_gemm_cell1, cudaFuncAttributeMaxDynamicSharedMemorySize,
                             G_SMEM);
        attr_set = true;
    }

    // preamble: 3 launches
    k_prep_all<<<PA_TOTAL, 256>>>(Wself, Wrel, x, mask, s_sc, r_sc, ei, et);
    k_sel<<<T_*C_ + T_ + SEL_DIS_BLOCKS, 1024, N_ * sizeof(uint32_t)>>>();
    k_zt_scatter<<<ZT_BLOCKS + T_*1250 + RZ_BLOCKS, 256>>>(x, ei, et);

    // t = 0 cells
    k_cell1_only<<<dim3(16, 1, 2*C_), 128>>>(sWz, sUz, sbz, sWr, sUr, sbr,
                                             rWz, rUz, rbz, rWr, rUr, rbr, 0, 0);
    k_cell2_only<<<dim3(16, 1, C_), 256>>>(sWh, sUh, sbh, rWh, rUh, rbh, 0, 0);

    // pipelined recurrence
    for (int t = 0; t < T_; t++) {
        int doCell = (t + 1 < T_) ? 1 : 0;
        int parN = (t + 1) & 1;
        k_gemm_cell1<<<dim3((N_ + 127)/128, 2, 2*C_ + C_), 128, G_SMEM>>>(
            out, t, sWz, sUz, sbz, sWr, sUr, sbr,
            rWz, rUz, rbz, rWr, rUr, rbr, parN, t + 1, doCell);
        k_agg_cell2<<<80 + 2500, 256>>>(
            out, t, sWh, sUh, sbh, rWh, rUh, rbh, parN, t + 1, doCell);
    }
}

// round 17
// speedup vs baseline: 1.0804x; 1.0031x over previous
#include <cuda_runtime.h>
#include <math.h>
#include <stdint.h>

#define T_ 3
#define N_ 20000
#define F_ 256
#define FO_ 256
#define E_ 320000
#define R_ 4
#define C_ 5
#define MAT_ (F_*FO_)

// ---------------- scratch ----------------
__device__ float g_scores[T_*C_*N_];
__device__ float g_vals  [T_*C_*FO_];
__device__ int   g_tidx  [T_*C_*FO_];
__device__ float g_zt    [T_*C_*MAT_];
__device__ float g_upd   [C_*MAT_];
__device__ float g_rst   [C_*MAT_];
__device__ float g_Q  [2][C_*MAT_];
__device__ float g_Qc    [C_*MAT_];
__device__ float g_xc    [T_*N_*F_];
__device__ float g_Y     [R_*N_*FO_];
__device__ int   g_degI  [T_*R_*N_];   // zero at entry (self-cleaned)
__device__ float g_dis   [T_*R_*N_];
__device__ int      g_cnt [T_*N_];     // zero at entry (self-cleaned)
__device__ int      g_off [T_*(N_+1)];
__device__ int      g_fill[T_*N_];
__device__ uint32_t g_epack[T_*E_];

extern __shared__ unsigned char s_dyn[];

__device__ __forceinline__ uint32_t f2key(float f) {
    uint32_t u = __float_as_uint(f);
    return (u & 0x80000000u) ? ~u : (u | 0x80000000u);
}
__device__ __forceinline__ float key2f(uint32_t k) {
    return (k & 0x80000000u) ? __uint_as_float(k & 0x7FFFFFFFu) : __uint_as_float(~k);
}
__device__ __forceinline__ float cvt_tf32(float f) {
    uint32_t r;
    asm("cvt.rna.tf32.f32 %0, %1;" : "=r"(r) : "f"(f));
    return __uint_as_float(r);
}
__device__ __forceinline__ float sigmoidf_(float v) { return 1.f / (1.f + expf(-v)); }

__device__ __forceinline__ void mma_tf32(float* d, const uint32_t* a, uint32_t b0, uint32_t b1) {
    asm volatile(
        "mma.sync.aligned.m16n8k8.row.col.f32.tf32.tf32.f32 "
        "{%0,%1,%2,%3}, {%4,%5,%6,%7}, {%8,%9}, {%0,%1,%2,%3};"
        : "+f"(d[0]), "+f"(d[1]), "+f"(d[2]), "+f"(d[3])
        : "r"(a[0]), "r"(a[1]), "r"(a[2]), "r"(a[3]), "r"(b0), "r"(b1));
}
__device__ __forceinline__ uint32_t smem_u32(const void* p) {
    uint32_t a;
    asm("{ .reg .u64 t; cvta.to.shared.u64 t, %1; cvt.u32.u64 %0, t; }" : "=r"(a) : "l"(p));
    return a;
}
__device__ __forceinline__ void cp_async16(uint32_t dst, const void* src) {
    asm volatile("cp.async.ca.shared.global [%0], [%1], 16;" :: "r"(dst), "l"(src) : "memory");
}
#define CP_COMMIT()  asm volatile("cp.async.commit_group;" ::: "memory")
#define CP_WAIT(n)   asm volatile("cp.async.wait_group %0;" :: "n"(n) : "memory")

// ================== L1: scores + edge count + initQ + xcvt ==================
#define PA_SCORE (T_*2500)
#define PA_CNT   (T_*1250)
#define PA_INIT  ((C_*MAT_)/256)
#define PA_XCVT  ((T_*N_*F_/4)/256)
#define PA_TOTAL (PA_SCORE + PA_CNT + PA_INIT + PA_XCVT)

__global__ __launch_bounds__(256) void k_prep_all(const float* __restrict__ Wself,
                                                  const float* __restrict__ Wrel,
                                                  const float* __restrict__ x,
                                                  const float* __restrict__ mask,
                                                  const float* __restrict__ s_sc,
                                                  const float* __restrict__ r_sc,
                                                  const int* __restrict__ ei,
                                                  const int* __restrict__ et) {
    int b = blockIdx.x, tid = threadIdx.x;
    if (b < PA_SCORE) {
        int t = b / 2500, blk = b - t*2500;
        __shared__ float sc[C_][F_];
        __shared__ float sden[C_];
        for (int i = tid; i < C_*F_; i += 256) {
            int c = i / F_, f = i - c*F_;
            sc[c][f] = (c == 0) ? s_sc[f] : r_sc[(c-1)*F_ + f];
        }
        __syncthreads();
        int warp = tid >> 5, lane = tid & 31;
        if (warp < C_) {
            float s = 0.f;
            #pragma unroll
            for (int q = 0; q < 8; q++) { float v = sc[warp][lane + q*32]; s += v*v; }
            for (int o = 16; o > 0; o >>= 1) s += __shfl_down_sync(0xffffffffu, s, o);
            if (lane == 0) sden[warp] = sqrtf(s) + 1e-8f;
        }
        __syncthreads();
        int n = blk * 8 + warp;
        if (n >= N_) return;
        const float4* xr = (const float4*)(x + ((size_t)t*N_ + n) * F_);
        float acc[C_] = {0.f, 0.f, 0.f, 0.f, 0.f};
        #pragma unroll
        for (int q = 0; q < 2; q++) {
            float4 xv = xr[lane + q*32];
            int e0 = (lane + q*32) * 4;
            #pragma unroll
            for (int c = 0; c < C_; c++) {
                acc[c] += xv.x * sc[c][e0]   + xv.y * sc[c][e0+1]
                        + xv.z * sc[c][e0+2] + xv.w * sc[c][e0+3];
            }
        }
        #pragma unroll
        for (int c = 0; c < C_; c++) {
            float v = acc[c];
            for (int o = 16; o > 0; o >>= 1) v += __shfl_down_sync(0xffffffffu, v, o);
            if (lane == 0)
                g_scores[(size_t)(t*C_ + c)*N_ + n] = v / sden[c] + mask[(size_t)t*N_ + n];
        }
    } else if (b < PA_SCORE + PA_CNT) {
        int idx = b - PA_SCORE;
        int t = idx / 1250;
        int e = (idx - t*1250)*256 + tid;
        if (e >= E_) return;
        int row = ei[(size_t)t*2*E_ + e];
        int r   = et[(size_t)t*E_ + e];
        atomicAdd(&g_degI[(t*R_ + r)*N_ + row], 1);
        atomicAdd(&g_cnt[t*N_ + row], 1);
    } else if (b < PA_SCORE + PA_CNT + PA_INIT) {
        int i = (b - PA_SCORE - PA_CNT)*256 + tid;
        int c = i / MAT_, off = i - c*MAT_;
        g_Q[0][i] = (c == 0) ? Wself[off] : Wrel[(c-1)*MAT_ + off];
    } else {
        int i = (b - PA_SCORE - PA_CNT - PA_INIT)*256 + tid;
        float4 v = ((const float4*)x)[i];
        v.x = cvt_tf32(v.x); v.y = cvt_tf32(v.y);
        v.z = cvt_tf32(v.z); v.w = cvt_tf32(v.w);
        ((float4*)g_xc)[i] = v;
    }
}

// ================== L2: topk + scan + dis ==================
__device__ void topk_body(int tc) {
    uint32_t* s_keys = (uint32_t*)s_dyn;
    __shared__ int      hist[256];
    __shared__ int      sfx[256];
    __shared__ uint32_t selKey[256];
    __shared__ int      selIdx[256];
    __shared__ uint32_t s_prefix;
    __shared__ int      s_remaining, s_eqCount, s_idxTh, s_cnt;

    int tid = threadIdx.x;
    const float* sc = g_scores + (size_t)tc * N_;

    if (tid < 256) hist[tid] = 0;
    if (tid == 0) { s_prefix = 0u; s_remaining = FO_; s_idxTh = 0x7FFFFFFF; s_eqCount = FO_; }
    __syncthreads();

    for (int i = tid; i < N_; i += 1024) {
        uint32_t k = f2key(sc[i]);
        s_keys[i] = k;
        atomicAdd(&hist[k >> 24], 1);
    }
    __syncthreads();

    #pragma unroll
    for (int pass = 3; pass >= 0; pass--) {
        int shift = pass * 8;
        if (pass < 3) {
            if (tid < 256) hist[tid] = 0;
            __syncthreads();
            uint32_t prefix = s_prefix;
            uint32_t pmask = 0xFFFFFFFFu << (shift + 8);
            for (int i = tid; i < N_; i += 1024) {
                uint32_t k = s_keys[i];
                if ((k & pmask) == (prefix & pmask))
                    atomicAdd(&hist[(k >> shift) & 0xFF], 1);
            }
            __syncthreads();
        }
        if (tid < 256) sfx[tid] = hist[tid];
        __syncthreads();
        #pragma unroll
        for (int o = 1; o < 256; o <<= 1) {
            int v = 0;
            if (tid < 256) v = sfx[tid] + ((tid + o < 256) ? sfx[tid + o] : 0);
            __syncthreads();
            if (tid < 256) sfx[tid] = v;
            __syncthreads();
        }
        int rem = s_remaining;
        __syncthreads();
        if (tid < 256) {
            int s  = sfx[tid];
            int sn = (tid < 255) ? sfx[tid + 1] : 0;
            if (s >= rem && sn < rem) {
                s_prefix |= ((uint32_t)tid) << shift;
                s_remaining = rem - sn;
                if (pass == 0) s_eqCount = hist[tid];
            }
        }
        __syncthreads();
    }
    uint32_t kth = s_prefix;
    int need = s_remaining;

    if (need < s_eqCount) {
        if (tid == 0) { s_prefix = 0u; s_remaining = need; }
        __syncthreads();
        #pragma unroll
        for (int pass = 1; pass >= 0; pass--) {
            int shift = pass * 8;
            if (tid < 256) hist[tid] = 0;
            __syncthreads();
            uint32_t prefixI = s_prefix;
            for (int i = tid; i < N_; i += 1024) {
                if (s_keys[i] == kth) {
                    if (pass == 1 || (((uint32_t)i >> 8) & 0xFF) == ((prefixI >> 8) & 0xFF))
                        atomicAdd(&hist[((uint32_t)i >> shift) & 0xFF], 1);
                }
            }
            __syncthreads();
            if (tid == 0) {
                int rem = s_remaining;
                uint32_t pfx = s_prefix;
                for (int bb = 0; bb < 256; bb++) {
                    int cnt = hist[bb];
                    if (cnt >= rem) { pfx |= ((uint32_t)bb) << shift; break; }
                    rem -= cnt;
                }
                s_remaining = rem;
                s_prefix = pfx;
            }
            __syncthreads();
        }
        if (tid == 0) s_idxTh = (int)s_prefix;
    }
    if (tid == 0) s_cnt = 0;
    __syncthreads();
    int idxTh = s_idxTh;

    for (int i = tid; i < N_; i += 1024) {
        uint32_t k = s_keys[i];
        if (k > kth || (k == kth && i <= idxTh)) {
            int p = atomicAdd(&s_cnt, 1);
            selKey[p] = k;
            selIdx[p] = i;
        }
    }
    __syncthreads();

    for (int k = 2; k <= 256; k <<= 1) {
        for (int j = k >> 1; j > 0; j >>= 1) {
            if (tid < 256) {
                int ixj = tid ^ j;
                if (ixj > tid) {
                    bool desc = ((tid & k) == 0);
                    uint32_t ka = selKey[tid], kb = selKey[ixj];
                    int ia = selIdx[tid], ib = selIdx[ixj];
                    bool aGreater = (ka > kb) || (ka == kb && ia < ib);
                    bool doswap = desc ? !aGreater : aGreater;
                    if (doswap) {
                        selKey[tid] = kb; selKey[ixj] = ka;
                        selIdx[tid] = ib; selIdx[ixj] = ia;
                    }
                }
            }
            __syncthreads();
        }
    }

    if (tid < 256) {
        g_vals[(size_t)tc*FO_ + tid] = key2f(selKey[tid]);
        g_tidx[(size_t)tc*FO_ + tid] = selIdx[tid];
    }
}

__device__ void scan_body(int t) {
    __shared__ int part[1024];
    const int* cnt = g_cnt + t*N_;
    int* off = g_off + t*(N_+1);
    int* fill = g_fill + t*N_;
    int tid = threadIdx.x;
    const int CH = (N_ + 1023) / 1024;
    int base = tid * CH;
    int s = 0;
    for (int i = 0; i < CH; i++) {
        int idx = base + i;
        if (idx < N_) s += cnt[idx];
    }
    part[tid] = s;
    __syncthreads();
    for (int o = 1; o < 1024; o <<= 1) {
        int v = (tid >= o) ? part[tid - o] : 0;
        __syncthreads();
        part[tid] += v;
        __syncthreads();
    }
    int run = (tid == 0) ? 0 : part[tid - 1];
    for (int i = 0; i < CH; i++) {
        int idx = base + i;
        if (idx < N_) {
            off[idx] = run;
            run += cnt[idx];
            fill[idx] = 0;
        }
    }
    if (tid == 0) off[N_] = E_;
}

#define SEL_DIS_BLOCKS (((T_*R_*N_)+1023)/1024)
__global__ __launch_bounds__(1024) void k_sel() {
    int b = blockIdx.x;
    if (b < T_*C_) {
        topk_body(b);
    } else if (b < T_*C_ + T_) {
        scan_body(b - T_*C_);
    } else {
        int i = (b - T_*C_ - T_)*1024 + threadIdx.x;
        if (i < T_*R_*N_) {
            int d = g_degI[i];
            g_dis[i] = (d > 0) ? (1.f / sqrtf((float)d)) : 0.f;
        }
    }
}

// ================== L3: zt + scatter + re-zero ==================
#define ZT_BLOCKS ((T_*C_*FO_)/4)
#define RZ_BLOCKS (((T_*R_*N_)+255)/256)
__global__ __launch_bounds__(256) void k_zt_scatter(const float* __restrict__ x,
                                                    const int* __restrict__ ei,
                                                    const int* __restrict__ et) {
    int b = blockIdx.x, tid = threadIdx.x;
    if (b < ZT_BLOCKS) {
        int sub = tid >> 6, l = tid & 63;
        int jct = b*4 + sub;
        int j = jct & 255;
        int cc = jct >> 8;
        int c = cc % C_, t = cc / C_;
        int tc = t*C_ + c;
        int idx = g_tidx[(size_t)tc*FO_ + j];
        float tv = tanhf(g_vals[(size_t)tc*FO_ + j]);
        const float4* xr = (const float4*)(x + ((size_t)t*N_ + idx) * F_);
        float4 v = xr[l];
        v.x *= tv; v.y *= tv; v.z *= tv; v.w *= tv;
        ((float4*)(g_zt + ((size_t)tc*FO_ + j) * F_))[l] = v;
    } else if (b < ZT_BLOCKS + T_*1250) {
        int idx = b - ZT_BLOCKS;
        int t = idx / 1250;
        int e = (idx - t*1250)*256 + tid;
        if (e >= E_) return;
        int row = ei[(size_t)t*2*E_ + e];
        int col = ei[(size_t)t*2*E_ + E_ + e];
        int r   = et[(size_t)t*E_ + e];
        int pos = g_off[t*(N_+1) + row] + atomicAdd(&g_fill[t*N_ + row], 1);
        g_epack[(size_t)t*E_ + pos] = ((uint32_t)col << 2) | (uint32_t)r;
    } else {
        int i = (b - ZT_BLOCKS - T_*1250)*256 + tid;
        if (i < T_*R_*N_) g_degI[i] = 0;
        if (i < T_*N_) g_cnt[i] = 0;
    }
}

// ================== cell1: cp.async double-buffered, k-chunk 32 (36.9 KB static) ==================
__device__ void cell1_body(const float* W, const float* U, const float* B,
                           const float* Z, const float* Qm, float* OUT, int x16) {
    __shared__ float sm1[2][4608];   // A [64*36]=2304 @0, B 2304 @2304
    int tid = threadIdx.x, lane = tid & 31, wid = tid >> 5;
    int wm = wid >> 1, wn = wid & 1;
    int grp = lane >> 2, tg = lane & 3;
    int i0 = (x16 >> 2) * 64, j0 = (x16 & 3) * 64;
    uint32_t smb[2] = { smem_u32(&sm1[0][0]), smem_u32(&sm1[1][0]) };

    float d[2][4][4];
    #pragma unroll
    for (int mt = 0; mt < 2; mt++)
        #pragma unroll
        for (int nt = 0; nt < 4; nt++)
            #pragma unroll
            for (int q = 0; q < 4; q++) d[mt][nt][q] = 0.f;

    auto load0 = [&](int stg, int kb) {
        uint32_t sa = smb[stg];
        #pragma unroll
        for (int i = 0; i < 4; i++) {
            int idx = tid + i*128;
            int row = idx >> 3, ch = (idx & 7) * 4;
            cp_async16(sa + (uint32_t)(row*36 + ch)*4, W + (size_t)(i0+row)*256 + kb + ch);
            cp_async16(sa + (uint32_t)(2304 + row*36 + ch)*4, Z + (size_t)(j0+row)*256 + kb + ch);
        }
        CP_COMMIT();
    };
    load0(0, 0);
    #pragma unroll 1
    for (int s = 0; s < 8; s++) {
        if (s + 1 < 8) load0((s + 1) & 1, (s + 1) * 32);
        if (s + 1 < 8) { CP_WAIT(1); } else { CP_WAIT(0); }
        __syncthreads();
        const float* As = sm1[s & 1];
        const float* Bs = As + 2304;
        #pragma unroll
        for (int kc = 0; kc < 4; kc++) {
            int k0 = kc * 8;
            uint32_t afr[2][4];
            #pragma unroll
            for (int mt = 0; mt < 2; mt++) {
                int mb = wm*32 + mt*16;
                afr[mt][0] = __float_as_uint(cvt_tf32(As[(mb+grp  )*36 + k0+tg  ]));
                afr[mt][1] = __float_as_uint(cvt_tf32(As[(mb+grp+8)*36 + k0+tg  ]));
                afr[mt][2] = __float_as_uint(cvt_tf32(As[(mb+grp  )*36 + k0+tg+4]));
                afr[mt][3] = __float_as_uint(cvt_tf32(As[(mb+grp+8)*36 + k0+tg+4]));
            }
            #pragma unroll
            for (int nt = 0; nt < 4; nt++) {
                int nb = wn*32 + nt*8;
                uint32_t b0 = __float_as_uint(cvt_tf32(Bs[(nb+grp)*36 + k0+tg  ]));
                uint32_t b1 = __float_as_uint(cvt_tf32(Bs[(nb+grp)*36 + k0+tg+4]));
                #pragma unroll
                for (int mt = 0; mt < 2; mt++) mma_tf32(d[mt][nt], afr[mt], b0, b1);
            }
        }
        __syncthreads();
    }

    auto load1 = [&](int stg, int kb) {
        uint32_t sa = smb[stg];
        #pragma unroll
        for (int i = 0; i < 4; i++) {
            int idx = tid + i*128;
            int row = idx >> 3, ch = (idx & 7) * 4;
            cp_async16(sa + (uint32_t)(row*36 + ch)*4, U + (size_t)(i0+row)*256 + kb + ch);
            int kr = idx >> 4, nc = (idx & 15) * 4;
            cp_async16(sa + (uint32_t)(2304 + kr*72 + nc)*4, Qm + (size_t)(kb+kr)*256 + j0 + nc);
        }
        CP_COMMIT();
    };
    load1(0, 0);
    #pragma unroll 1
    for (int s = 0; s < 8; s++) {
        if (s + 1 < 8) load1((s + 1) & 1, (s + 1) * 32);
        if (s + 1 < 8) { CP_WAIT(1); } else { CP_WAIT(0); }
        __syncthreads();
        const float* As = sm1[s & 1];
        const float* Bs = As + 2304;
        #pragma unroll
        for (int kc = 0; kc < 4; kc++) {
            int k0 = kc * 8;
            uint32_t afr[2][4];
            #pragma unroll
            for (int mt = 0; mt < 2; mt++) {
                int mb = wm*32 + mt*16;
                afr[mt][0] = __float_as_uint(cvt_tf32(As[(mb+grp  )*36 + k0+tg  ]));
                afr[mt][1] = __float_as_uint(cvt_tf32(As[(mb+grp+8)*36 + k0+tg  ]));
                afr[mt][2] = __float_as_uint(cvt_tf32(As[(mb+grp  )*36 + k0+tg+4]));
                afr[mt][3] = __float_as_uint(cvt_tf32(As[(mb+grp+8)*36 + k0+tg+4]));
            }
            #pragma unroll
            for (int nt = 0; nt < 4; nt++) {
                int nb = wn*32 + nt*8;
                uint32_t b0 = __float_as_uint(cvt_tf32(Bs[(k0+tg  )*72 + nb+grp]));
                uint32_t b1 = __float_as_uint(cvt_tf32(Bs[(k0+tg+4)*72 + nb+grp]));
                #pragma unroll
                for (int mt = 0; mt < 2; mt++) mma_tf32(d[mt][nt], afr[mt], b0, b1);
            }
        }
        __syncthreads();
    }

    #pragma unroll
    for (int mt = 0; mt < 2; mt++) {
        #pragma unroll
        for (int nt = 0; nt < 4; nt++) {
            int r0 = i0 + wm*32 + mt*16 + grp;
            int col = j0 + wn*32 + nt*8 + 2*tg;
            float2 bi0 = *(const float2*)(B + (size_t)r0*256 + col);
            *(float2*)&OUT[(size_t)r0*256 + col] =
                make_float2(sigmoidf_(d[mt][nt][0] + bi0.x), sigmoidf_(d[mt][nt][1] + bi0.y));
            int r1 = r0 + 8;
            float2 bi1 = *(const float2*)(B + (size_t)r1*256 + col);
            *(float2*)&OUT[(size_t)r1*256 + col] =
                make_float2(sigmoidf_(d[mt][nt][2] + bi1.x), sigmoidf_(d[mt][nt][3] + bi1.y));
        }
    }
}

// ================== cell2: cp.async double-buffered, k-chunk 16 (28.7 KB static, R15 body) ==================
__device__ void cell2_body(const float* W, const float* U, const float* B,
                           const float* Z, const float* Qin, const float* RST,
                           const float* UPD, float* Qout, float* Qc, int x16) {
    __shared__ float sm2[2][3584];   // A 1280 @0, B 1280 @1280, R 1152 @2432 (phase1)
    int tid = threadIdx.x, lane = tid & 31, wid = tid >> 5;
    int wm = wid >> 2, wn = wid & 3;
    int grp = lane >> 2, tg = lane & 3;
    int i0 = (x16 >> 2) * 64, j0 = (x16 & 3) * 64;
    uint32_t smb[2] = { smem_u32(&sm2[0][0]), smem_u32(&sm2[1][0]) };

    float d[2][2][4];
    #pragma unroll
    for (int mt = 0; mt < 2; mt++)
        #pragma unroll
        for (int nt = 0; nt < 2; nt++)
            #pragma unroll
            for (int q = 0; q < 4; q++) d[mt][nt][q] = 0.f;

    auto load0 = [&](int stg, int kb) {
        uint32_t sa = smb[stg];
        int idx = tid;
        int row = idx >> 2, ch = (idx & 3) * 4;
        cp_async16(sa + (uint32_t)(row*20 + ch)*4, W + (size_t)(i0+row)*256 + kb + ch);
        cp_async16(sa + (uint32_t)(1280 + row*20 + ch)*4, Z + (size_t)(j0+row)*256 + kb + ch);
        CP_COMMIT();
    };
    load0(0, 0);
    #pragma unroll 1
    for (int s = 0; s < 16; s++) {
        if (s + 1 < 16) load0((s + 1) & 1, (s + 1) * 16);
        if (s + 1 < 16) { CP_WAIT(1); } else { CP_WAIT(0); }
        __syncthreads();
        const float* As = sm2[s & 1];
        const float* Bs = As + 1280;
        #pragma unroll
        for (int kc = 0; kc < 2; kc++) {
            int k0 = kc * 8;
            uint32_t afr[2][4];
            #pragma unroll
            for (int mt = 0; mt < 2; mt++) {
                int mb = wm*32 + mt*16;
                afr[mt][0] = __float_as_uint(cvt_tf32(As[(mb+grp  )*20 + k0+tg  ]));
                afr[mt][1] = __float_as_uint(cvt_tf32(As[(mb+grp+8)*20 + k0+tg  ]));
                afr[mt][2] = __float_as_uint(cvt_tf32(As[(mb+grp  )*20 + k0+tg+4]));
                afr[mt][3] = __float_as_uint(cvt_tf32(As[(mb+grp+8)*20 + k0+tg+4]));
            }
            #pragma unroll
            for (int nt = 0; nt < 2; nt++) {
                int nb = wn*16 + nt*8;
                uint32_t b0 = __float_as_uint(cvt_tf32(Bs[(nb+grp)*20 + k0+tg  ]));
                uint32_t b1 = __float_as_uint(cvt_tf32(Bs[(nb+grp)*20 + k0+tg+4]));
                #pragma unroll
                for (int mt = 0; mt < 2; mt++) mma_tf32(d[mt][nt], afr[mt], b0, b1);
            }
        }
        __syncthreads();
    }

    auto load1 = [&](int stg, int kb) {
        uint32_t sa = smb[stg];
        int idx = tid;
        int row = idx >> 2, ch = (idx & 3) * 4;
        cp_async16(sa + (uint32_t)(row*20 + ch)*4, U + (size_t)(i0+row)*256 + kb + ch);
        int kr = idx >> 4, nc = (idx & 15) * 4;
        cp_async16(sa + (uint32_t)(1280 + kr*72 + nc)*4, Qin + (size_t)(kb+kr)*256 + j0 + nc);
        cp_async16(sa + (uint32_t)(2432 + kr*72 + nc)*4, RST + (size_t)(kb+kr)*256 + j0 + nc);
        CP_COMMIT();
    };
    load1(0, 0);
    #pragma unroll 1
    for (int s = 0; s < 16; s++) {
        if (s + 1 < 16) load1((s + 1) & 1, (s + 1) * 16);
        if (s + 1 < 16) { CP_WAIT(1); } else { CP_WAIT(0); }
        __syncthreads();
        const float* As = sm2[s & 1];
        const float* Bq = As + 1280;
        const float* Br = As + 2432;
        #pragma unroll
        for (int kc = 0; kc < 2; kc++) {
            int k0 = kc * 8;
            uint32_t afr[2][4];
            #pragma unroll
            for (int mt = 0; mt < 2; mt++) {
                int mb = wm*32 + mt*16;
                afr[mt][0] = __float_as_uint(cvt_tf32(As[(mb+grp  )*20 + k0+tg  ]));
                afr[mt][1] = __float_as_uint(cvt_tf32(As[(mb+grp+8)*20 + k0+tg  ]));
                afr[mt][2] = __float_as_uint(cvt_tf32(As[(mb+grp  )*20 + k0+tg+4]));
                afr[mt][3] = __float_as_uint(cvt_tf32(As[(mb+grp+8)*20 + k0+tg+4]));
            }
            #pragma unroll
            for (int nt = 0; nt < 2; nt++) {
                int nb = wn*16 + nt*8;
                uint32_t b0 = __float_as_uint(cvt_tf32(Bq[(k0+tg  )*72 + nb+grp] * Br[(k0+tg  )*72 + nb+grp]));
                uint32_t b1 = __float_as_uint(cvt_tf32(Bq[(k0+tg+4)*72 + nb+grp] * Br[(k0+tg+4)*72 + nb+grp]));
                #pragma unroll
                for (int mt = 0; mt < 2; mt++) mma_tf32(d[mt][nt], afr[mt], b0, b1);
            }
        }
        __syncthreads();
    }

    #pragma unroll
    for (int mt = 0; mt < 2; mt++) {
        #pragma unroll
        for (int nt = 0; nt < 2; nt++) {
            #pragma unroll
            for (int half = 0; half < 2; half++) {
                int r = i0 + wm*32 + mt*16 + grp + half*8;
                int col = j0 + wn*16 + nt*8 + 2*tg;
                float d0 = d[mt][nt][half*2], d1 = d[mt][nt][half*2 + 1];
                float2 bi = *(const float2*)(B + (size_t)r*256 + col);
                float2 up = *(const float2*)(UPD + (size_t)r*256 + col);
                float2 qi = *(const float2*)(Qin + (size_t)r*256 + col);
                float h0 = tanhf(d0 + bi.x), h1 = tanhf(d1 + bi.y);
                float v0 = (1.f - up.x)*qi.x + up.x*h0;
                float v1 = (1.f - up.y)*qi.y + up.y*h1;
                *(float2*)&Qout[(size_t)r*256 + col] = make_float2(v0, v1);
                *(float2*)&Qc[(size_t)r*256 + col] = make_float2(cvt_tf32(v0), cvt_tf32(v1));
            }
        }
    }
}

__device__ __forceinline__ void cell1_sel(
    int o, int c,
    const float* sWz, const float* sUz, const float* sbz,
    const float* sWr, const float* sUr, const float* sbr,
    const float* rWz, const float* rUz, const float* rbz,
    const float* rWr, const float* rUr, const float* rbr,
    int par, int t, int x16) {
    const float *W, *U, *B;
    if (o == 0) { W = c ? rWz + (c-1)*MAT_ : sWz; U = c ? rUz + (c-1)*MAT_ : sUz; B = c ? rbz + (c-1)*MAT_ : sbz; }
    else        { W = c ? rWr + (c-1)*MAT_ : sWr; U = c ? rUr + (c-1)*MAT_ : sUr; B = c ? rbr + (c-1)*MAT_ : sbr; }
    cell1_body(W, U, B, g_zt + (size_t)(t*C_ + c)*MAT_, g_Q[par] + c*MAT_,
               (o == 0 ? g_upd : g_rst) + c*MAT_, x16);
}

__global__ __launch_bounds__(128) void k_cell1_only(
    const float* sWz, const float* sUz, const float* sbz,
    const float* sWr, const float* sUr, const float* sbr,
    const float* rWz, const float* rUz, const float* rbz,
    const float* rWr, const float* rUr, const float* rbr,
    int par, int t) {
    int u = blockIdx.z;
    cell1_sel(u & 1, u >> 1, sWz, sUz, sbz, sWr, sUr, sbr,
              rWz, rUz, rbz, rWr, rUr, rbr, par, t, blockIdx.x);
}
__global__ __launch_bounds__(256) void k_cell2_only(
    const float* sWh, const float* sUh, const float* sbh,
    const float* rWh, const float* rUh, const float* rbh,
    int par, int t) {
    int c = blockIdx.z;
    const float* W = c ? rWh + (c-1)*MAT_ : sWh;
    const float* U = c ? rUh + (c-1)*MAT_ : sUh;
    const float* B = c ? rbh + (c-1)*MAT_ : sbh;
    cell2_body(W, U, B, g_zt + (size_t)(t*C_ + c)*MAT_,
               g_Q[par] + c*MAT_, g_rst + c*MAT_, g_upd + c*MAT_,
               g_Q[par ^ 1] + c*MAT_, g_Qc + c*MAT_, blockIdx.x);
}

// ================== big GEMM: 128x128 tile, 128 threads, 3-stage cp.async ==================
#define GA_PAD 20
#define GB_PAD 136
#define G_STAGE (128*GA_PAD*4 + 16*GB_PAD*4)
#define G_NSTG  3
#define G_SMEM  (G_NSTG*G_STAGE)

__device__ void gemm_body(float* __restrict__ out, int t, int c, int m0, int n0) {
    const float* Ag = g_xc + (size_t)t*N_*F_;
    const float* Bg = g_Qc + (size_t)c*MAT_;
    float* dst = (c == 0) ? out + (size_t)t*N_*FO_ : g_Y + (size_t)(c-1)*N_*FO_;

    float* smf = (float*)s_dyn;
    uint32_t smb = smem_u32(s_dyn);
    int tid = threadIdx.x, wid = tid >> 5, lane = tid & 31;
    int wm = wid >> 1, wn = wid & 1;
    int grp = lane >> 2, tg = lane & 3;

    float d[4][8][4];
    #pragma unroll
    for (int mt = 0; mt < 4; mt++)
        #pragma unroll
        for (int nt = 0; nt < 8; nt++)
            #pragma unroll
            for (int q = 0; q < 4; q++) d[mt][nt][q] = 0.f;

    auto load_stage = [&](int stg, int kb) {
        uint32_t sa = smb + stg*G_STAGE;
        uint32_t sb = sa + 128*GA_PAD*4;
        #pragma unroll
        for (int i = 0; i < 4; i++) {
            int idx = tid + i*128;
            int row = idx >> 2, ch = idx & 3;
            int gr = m0 + row;
            uint32_t dsta = sa + (uint32_t)(row*GA_PAD + ch*4)*4;
            if (gr < N_) {
                cp_async16(dsta, Ag + (size_t)gr*F_ + kb + ch*4);
            } else {
                *(float4*)(s_dyn + (dsta - smb)) = make_float4(0.f, 0.f, 0.f, 0.f);
            }
        }
        #pragma unroll
        for (int i = 0; i < 4; i++) {
            int idx = tid + i*128;
            int kr = idx >> 5, nch = idx & 31;
            uint32_t dstb = sb + (uint32_t)(kr*GB_PAD + nch*4)*4;
            cp_async16(dstb, Bg + (size_t)(kb + kr)*FO_ + n0 + nch*4);
        }
        CP_COMMIT();
    };

    load_stage(0, 0);
    load_stage(1, 16);

    #pragma unroll 1
    for (int step = 0; step < 16; step++) {
        if (step + 2 < 16) load_stage((step + 2) % G_NSTG, (step + 2) * 16);
        if (step + 2 < 16)      { CP_WAIT(2); }
        else if (step + 1 < 16) { CP_WAIT(1); }
        else                    { CP_WAIT(0); }
        __syncthreads();

        const float* As = smf + (step % G_NSTG) * (G_STAGE/4);
        const float* Bs = As + 128*GA_PAD;

        #pragma unroll
        for (int kc = 0; kc < 2; kc++) {
            int k0 = kc * 8;
            uint32_t a[4][4];
            #pragma unroll
            for (int mt = 0; mt < 4; mt++) {
                int mb = wm*64 + mt*16;
                a[mt][0] = __float_as_uint(As[(mb + grp    )*GA_PAD + k0 + tg    ]);
                a[mt][1] = __float_as_uint(As[(mb + grp + 8)*GA_PAD + k0 + tg    ]);
                a[mt][2] = __float_as_uint(As[(mb + grp    )*GA_PAD + k0 + tg + 4]);
                a[mt][3] = __float_as_uint(As[(mb + grp + 8)*GA_PAD + k0 + tg + 4]);
            }
            #pragma unroll
            for (int nt = 0; nt < 8; nt++) {
                int nb = wn*64 + nt*8;
                uint32_t b0 = __float_as_uint(Bs[(k0 + tg    )*GB_PAD + nb + grp]);
                uint32_t b1 = __float_as_uint(Bs[(k0 + tg + 4)*GB_PAD + nb + grp]);
                #pragma unroll
                for (int mt = 0; mt < 4; mt++)
                    mma_tf32(d[mt][nt], a[mt], b0, b1);
            }
        }
        __syncthreads();
    }

    #pragma unroll
    for (int mt = 0; mt < 4; mt++) {
        #pragma unroll
        for (int nt = 0; nt < 8; nt++) {
            int r0 = m0 + wm*64 + mt*16 + grp;
            int col = n0 + wn*64 + nt*8 + 2*tg;
            if (r0 < N_)
                *(float2*)&dst[(size_t)r0*FO_ + col] = make_float2(d[mt][nt][0], d[mt][nt][1]);
            int r1 = r0 + 8;
            if (r1 < N_)
                *(float2*)&dst[(size_t)r1*FO_ + col] = make_float2(d[mt][nt][2], d[mt][nt][3]);
        }
    }
}

// ================== agg body: 1 warp per row ==================
__device__ void agg_body(float* __restrict__ out, int t, int blk) {
    int warp = threadIdx.x >> 5, lane = threadIdx.x & 31;
    int row = blk * 8 + warp;
    if (row >= N_) return;
    const float* dis = g_dis + (size_t)t*R_*N_;
    float disrow[R_];
    #pragma unroll
    for (int r = 0; r < R_; r++) disrow[r] = dis[r*N_ + row];
    float4 a0 = make_float4(0.f, 0.f, 0.f, 0.f);
    float4 a1 = make_float4(0.f, 0.f, 0.f, 0.f);
    int beg = g_off[t*(N_+1) + row], end = g_off[t*(N_+1) + row + 1];
    const uint32_t* ep = g_epack + (size_t)t*E_;
    for (int p = beg; p < end; p++) {
        uint32_t pk = ep[p];
        int r = pk & 3;
        int col = pk >> 2;
        float norm = disrow[r] * dis[r*N_ + col];
        if (norm != 0.f) {
            const float4* src = (const float4*)(g_Y + ((size_t)r*N_ + col) * FO_);
            float4 v0 = src[lane];
            float4 v1 = src[lane + 32];
            a0.x += v0.x*norm; a0.y += v0.y*norm; a0.z += v0.z*norm; a0.w += v0.w*norm;
            a1.x += v1.x*norm; a1.y += v1.y*norm; a1.z += v1.z*norm; a1.w += v1.w*norm;
        }
    }
    float4* dst = (float4*)(out + (size_t)t*N_*FO_ + (size_t)row*FO_);
    float4 o0 = dst[lane];
    float4 o1 = dst[lane + 32];
    o0.x = fmaxf(o0.x + a0.x, 0.f); o0.y = fmaxf(o0.y + a0.y, 0.f);
    o0.z = fmaxf(o0.z + a0.z, 0.f); o0.w = fmaxf(o0.w + a0.w, 0.f);
    o1.x = fmaxf(o1.x + a1.x, 0.f); o1.y = fmaxf(o1.y + a1.y, 0.f);
    o1.z = fmaxf(o1.z + a1.z, 0.f); o1.w = fmaxf(o1.w + a1.w, 0.f);
    dst[lane] = o0;
    dst[lane + 32] = o1;
}

// ================== merged per-t kernels (cells at LOW block indices) ==================
__global__ __launch_bounds__(128, 2) void k_gemm_cell1(
    float* __restrict__ out, int t,
    const float* sWz, const float* sUz, const float* sbz,
    const float* sWr, const float* sUr, const float* sbr,
    const float* rWz, const float* rUz, const float* rbz,
    const float* rWr, const float* rUr, const float* rbr,
    int parNext, int tNext, int doCell) {
    int z = blockIdx.z;
    if (z < 2*C_) {
        if (!doCell || blockIdx.x >= 16 || blockIdx.y != 0) return;
        cell1_sel(z & 1, z >> 1, sWz, sUz, sbz, sWr, sUr, sbr,
                  rWz, rUz, rbz, rWr, rUr, rbr, parNext, tNext, blockIdx.x);
    } else {
        gemm_body(out, t, z - 2*C_, blockIdx.x * 128, blockIdx.y * 128);
    }
}

__global__ __launch_bounds__(256) void k_agg_cell2(
    float* __restrict__ out, int t,
    const float* sWh, const float* sUh, const float* sbh,
    const float* rWh, const float* rUh, const float* rbh,
    int parNext, int tNext, int doCell) {
    int x = blockIdx.x;
    if (x < 80) {
        if (!doCell) return;
        int c = x >> 4, x16 = x & 15;
        const float* W = c ? rWh + (c-1)*MAT_ : sWh;
        const float* U = c ? rUh + (c-1)*MAT_ : sUh;
        const float* B = c ? rbh + (c-1)*MAT_ : sbh;
        cell2_body(W, U, B, g_zt + (size_t)(tNext*C_ + c)*MAT_,
                   g_Q[parNext] + c*MAT_, g_rst + c*MAT_, g_upd + c*MAT_,
                   g_Q[parNext ^ 1] + c*MAT_, g_Qc + c*MAT_, x16);
    } else {
        agg_body(out, t, x - 80);
    }
}

// ================== launcher ==================
extern "C" void kernel_launch(void* const* d_in, const int* in_sizes, int n_in,
                              void* d_out, int out_size) {
    const float* x       = (const float*)d_in[0];
    const float* mask    = (const float*)d_in[1];
    const float* Wself   = (const float*)d_in[2];
    const float* Wrel    = (const float*)d_in[3];
    const float* sWz     = (const float*)d_in[4];
    const float* sUz     = (const float*)d_in[5];
    const float* sbz     = (const float*)d_in[6];
    const float* sWr     = (const float*)d_in[7];
    const float* sUr     = (const float*)d_in[8];
    const float* sbr     = (const float*)d_in[9];
    const float* sWh     = (const float*)d_in[10];
    const float* sUh     = (const float*)d_in[11];
    const float* sbh     = (const float*)d_in[12];
    const float* s_sc    = (const float*)d_in[13];
    const float* rWz     = (const float*)d_in[14];
    const float* rUz     = (const float*)d_in[15];
    const float* rbz     = (const float*)d_in[16];
    const float* rWr     = (const float*)d_in[17];
    const float* rUr     = (const float*)d_in[18];
    const float* rbr     = (const float*)d_in[19];
    const float* rWh     = (const float*)d_in[20];
    const float* rUh     = (const float*)d_in[21];
    const float* rbh     = (const float*)d_in[22];
    const float* r_sc    = (const float*)d_in[23];
    const int*   ei      = (const int*)d_in[24];
    const int*   et      = (const int*)d_in[25];
    float* out = (float*)d_out;

    static bool attr_set = false;
    if (!attr_set) {
        cudaFuncSetAttribute(k_sel, cudaFuncAttributeMaxDynamicSharedMemorySize,
                             N_ * (int)sizeof(uint32_t));
        cudaFuncSetAttribute(k_gemm_cell1, cudaFuncAttributeMaxDynamicSharedMemorySize,
                             G_SMEM);
        attr_set = true;
    }

    // preamble: 3 launches
    k_prep_all<<<PA_TOTAL, 256>>>(Wself, Wrel, x, mask, s_sc, r_sc, ei, et);
    k_sel<<<T_*C_ + T_ + SEL_DIS_BLOCKS, 1024, N_ * sizeof(uint32_t)>>>();
    k_zt_scatter<<<ZT_BLOCKS + T_*1250 + RZ_BLOCKS, 256>>>(x, ei, et);

    // t = 0 cells
    k_cell1_only<<<dim3(16, 1, 2*C_), 128>>>(sWz, sUz, sbz, sWr, sUr, sbr,
                                             rWz, rUz, rbz, rWr, rUr, rbr, 0, 0);
    k_cell2_only<<<dim3(16, 1, C_), 256>>>(sWh, sUh, sbh, rWh, rUh, rbh, 0, 0);

    // pipelined recurrence
    for (int t = 0; t < T_; t++) {
        int doCell = (t + 1 < T_) ? 1 : 0;
        int parN = (t + 1) & 1;
        k_gemm_cell1<<<dim3((N_ + 127)/128, 2, 2*C_ + C_), 128, G_SMEM>>>(
            out, t, sWz, sUz, sbz, sWr, sUr, sbr,
            rWz, rUz, rbz, rWr, rUr, rbr, parN, t + 1, doCell);
        k_agg_cell2<<<80 + 2500, 256>>>(
            out, t, sWh, sUh, sbh, rWh, rUh, rbh, parN, t + 1, doCell);
    }
}